// round 1
// baseline (speedup 1.0000x reference)
#include <cuda_runtime.h>
#include <cstdint>
#include <cstddef>

// ---------------------------------------------------------------------------
// GCN_27874337751415: 3-layer GCN + mean-pool + linear head, fp32.
//   h = relu(Ahat (x@W1) + b1); h = relu(Ahat (h@W2) + b2); h = Ahat (h@W3) + b3
//   out = mean_pool_by_batch(h) @ Wl + bl
// Ahat = D^-1/2 (A + I) D^-1/2, deg = in-degree(dst) + 1.
// ---------------------------------------------------------------------------

#define MAXN 50176
#define MAXE 800000

__device__ int   g_deg[MAXN];
__device__ float g_dinv[MAXN];
__device__ int   g_off[MAXN + 1];
__device__ int   g_cur[MAXN];
__device__ int   g_bs[1024];
__device__ int   g_bs2[1024];
__device__ int   g_src[MAXE];
__device__ float g_wt[MAXE];
__device__ float g_H[(size_t)MAXN * 256];
__device__ float g_A[(size_t)MAXN * 256];
__device__ float g_pool[64 * 64];
__device__ float g_cnt[64];
__device__ int   g_ei64;   // 1 if edge_index is int64, 0 if int32
__device__ int   g_b64;    // 1 if batch is int64, 0 if int32

// ---------------------------------------------------------------------------
// dtype detection: int64 little-endian with values < 2^31 has zero high words.
// edge head is random (never all-zero as int32); batch is SORTED so probe its
// middle (values ~G/2, nonzero) and stay in-bounds for the int32 case.
// ---------------------------------------------------------------------------
__global__ void k_detect(const unsigned* __restrict__ ei,
                         const unsigned* __restrict__ bat, int E, int N) {
    __shared__ int s_ei, s_b;
    if (threadIdx.x == 0) { s_ei = 0; s_b = 0; }
    __syncthreads();
    int ne = (E < 1024) ? E : 1024;
    for (int i = threadIdx.x; i < ne; i += blockDim.x)
        if (ei[2 * i + 1]) atomicOr(&s_ei, 1);
    int base = N / 2 - 256; if (base < 0) base = 0;
    int nb2 = (N / 2 > 256) ? 256 : N / 2;
    for (int j = threadIdx.x; j < nb2; j += blockDim.x)
        if (bat[2 * (base + j) + 1]) atomicOr(&s_b, 1);
    __syncthreads();
    if (threadIdx.x == 0) { g_ei64 = s_ei ? 0 : 1; g_b64 = s_b ? 0 : 1; }
}

__device__ __forceinline__ int load_idx(const void* p, int i, int is64) {
    return is64 ? (int)((const long long*)p)[i] : ((const int*)p)[i];
}

// ---------------------------------------------------------------------------
// Degree histogram over dst, dinv = rsqrt(deg+1)
// ---------------------------------------------------------------------------
__global__ void k_hist(const void* __restrict__ ei, int E) {
    int e = blockIdx.x * blockDim.x + threadIdx.x;
    if (e >= E) return;
    int is64 = g_ei64;
    int d = load_idx(ei, E + e, is64);
    atomicAdd(&g_deg[d], 1);
}

__global__ void k_dinv(int N) {
    int v = blockIdx.x * blockDim.x + threadIdx.x;
    if (v >= N) return;
    g_dinv[v] = rsqrtf((float)(g_deg[v] + 1));
}

// ---------------------------------------------------------------------------
// Exclusive scan of g_deg -> g_off (3-kernel: block scan, top scan, add)
// ---------------------------------------------------------------------------
__global__ void k_scan(const int* __restrict__ in, int* __restrict__ out,
                       int* __restrict__ bsum, int n) {
    __shared__ int s[1024];
    int gid = blockIdx.x * 1024 + threadIdx.x;
    int v = (gid < n) ? in[gid] : 0;
    s[threadIdx.x] = v;
    __syncthreads();
    #pragma unroll
    for (int d = 1; d < 1024; d <<= 1) {
        int t = (threadIdx.x >= d) ? s[threadIdx.x - d] : 0;
        __syncthreads();
        s[threadIdx.x] += t;
        __syncthreads();
    }
    if (gid < n) out[gid] = s[threadIdx.x] - v;  // exclusive
    if (bsum != nullptr && threadIdx.x == 1023) bsum[blockIdx.x] = s[1023];
}

__global__ void k_scanadd(int* __restrict__ off, const int* __restrict__ bs2,
                          int n, int E) {
    int gid = blockIdx.x * 1024 + threadIdx.x;
    if (gid < n) off[gid] += bs2[blockIdx.x];
    if (gid == 0) off[n] = E;
}

// ---------------------------------------------------------------------------
// Scatter edges into CSR-by-dst, weight = dinv[src]
// ---------------------------------------------------------------------------
__global__ void k_scatter(const void* __restrict__ ei, int E) {
    int e = blockIdx.x * blockDim.x + threadIdx.x;
    if (e >= E) return;
    int is64 = g_ei64;
    int s = load_idx(ei, e, is64);
    int d = load_idx(ei, E + e, is64);
    int p = atomicAdd(&g_cur[d], 1);
    g_src[p] = s;
    g_wt[p] = g_dinv[s];
}

// ---------------------------------------------------------------------------
// GEMM: C[M,N] = A[M,K] @ B[K,N], fp32 via packed fma.rn.f32x2.
// Tile 128x64x16, 256 threads, 8x4 per thread (16 u64 accumulators).
// B tile stored element-duplicated in smem so (b,b) pairs are direct LDS.
// ---------------------------------------------------------------------------
__device__ __forceinline__ unsigned long long ffma2(unsigned long long a,
                                                    unsigned long long b,
                                                    unsigned long long c) {
    unsigned long long d;
    asm("fma.rn.f32x2 %0, %1, %2, %3;" : "=l"(d) : "l"(a), "l"(b), "l"(c));
    return d;
}

#define GBM 128
#define GBN 64
#define GBK 16

__global__ __launch_bounds__(256, 2) void k_gemm(const float* __restrict__ A,
                                                 const float* __restrict__ B,
                                                 float* __restrict__ C,
                                                 int M, int N, int K) {
    __shared__ float As[GBK][GBM + 4];     // transposed: As[k][m], padded row
    __shared__ float Bs[GBK][GBN * 2];     // duplicated: b0,b0,b1,b1,...

    int tid = threadIdx.x;
    int bm = blockIdx.x * GBM, bn = blockIdx.y * GBN;
    int tx = tid & 15, ty = tid >> 4;

    unsigned long long acc[4][4];
    #pragma unroll
    for (int i = 0; i < 4; i++)
        #pragma unroll
        for (int j = 0; j < 4; j++) acc[i][j] = 0ull;

    int brow = tid >> 4, bcol = (tid & 15) * 4;

    for (int k0 = 0; k0 < K; k0 += GBK) {
        // A tile: 128x16 = 512 float4, 2 per thread (store transposed)
        #pragma unroll
        for (int u = 0; u < 2; u++) {
            int idx = tid * 2 + u;
            int row = idx >> 2;
            int c4 = (idx & 3) * 4;
            float4 av = make_float4(0.f, 0.f, 0.f, 0.f);
            int gr = bm + row;
            if (gr < M) av = *(const float4*)(A + (size_t)gr * K + (k0 + c4));
            As[c4 + 0][row] = av.x;
            As[c4 + 1][row] = av.y;
            As[c4 + 2][row] = av.z;
            As[c4 + 3][row] = av.w;
        }
        // B tile: 16x64 = 256 float4, 1 per thread, duplicated store
        {
            float4 bv = *(const float4*)(B + (size_t)(k0 + brow) * N + (bn + bcol));
            float* d = &Bs[brow][bcol * 2];
            *(float4*)(d)     = make_float4(bv.x, bv.x, bv.y, bv.y);
            *(float4*)(d + 4) = make_float4(bv.z, bv.z, bv.w, bv.w);
        }
        __syncthreads();

        #pragma unroll
        for (int kk = 0; kk < GBK; kk++) {
            ulonglong2 aL = *(const ulonglong2*)&As[kk][ty * 8];
            ulonglong2 aH = *(const ulonglong2*)&As[kk][ty * 8 + 4];
            ulonglong2 bL = *(const ulonglong2*)&Bs[kk][tx * 8];
            ulonglong2 bH = *(const ulonglong2*)&Bs[kk][tx * 8 + 4];
            unsigned long long a[4] = {aL.x, aL.y, aH.x, aH.y};
            unsigned long long b[4] = {bL.x, bL.y, bH.x, bH.y};
            #pragma unroll
            for (int i = 0; i < 4; i++)
                #pragma unroll
                for (int j = 0; j < 4; j++)
                    acc[i][j] = ffma2(a[i], b[j], acc[i][j]);
        }
        __syncthreads();
    }

    // epilogue: acc[rp][j] packs rows (ty*8+2rp, +1), col tx*4+j
    #pragma unroll
    for (int rp = 0; rp < 4; rp++) {
        float2 c0 = *(float2*)&acc[rp][0];
        float2 c1 = *(float2*)&acc[rp][1];
        float2 c2 = *(float2*)&acc[rp][2];
        float2 c3 = *(float2*)&acc[rp][3];
        int r0 = bm + ty * 8 + rp * 2;
        if (r0 < M) {
            float4 o = make_float4(c0.x, c1.x, c2.x, c3.x);
            *(float4*)(C + (size_t)r0 * N + bn + tx * 4) = o;
        }
        if (r0 + 1 < M) {
            float4 o = make_float4(c0.y, c1.y, c2.y, c3.y);
            *(float4*)(C + (size_t)(r0 + 1) * N + bn + tx * 4) = o;
        }
    }
}

// ---------------------------------------------------------------------------
// Aggregation: Out[v] = dinv[v]*(dinv[v]*H[v] + sum_e wt[e]*H[src[e]]) + bias
// blockDim.x = F/4 (float4 lanes), blockDim.y = nodes per block.
// ---------------------------------------------------------------------------
__global__ void k_agg(const float* __restrict__ Hin, float* __restrict__ Out,
                      const float* __restrict__ bias, int N, int relu) {
    int v = blockIdx.x * blockDim.y + threadIdx.y;
    if (v >= N) return;
    int F4 = blockDim.x;
    int x = threadIdx.x;
    const float4* H4 = (const float4*)Hin;
    float dv = g_dinv[v];
    float4 hv = H4[(size_t)v * F4 + x];
    float4 acc = make_float4(dv * hv.x, dv * hv.y, dv * hv.z, dv * hv.w);
    int e = g_off[v], end = g_off[v + 1];
    for (; e < end; e++) {
        int s = __ldg(&g_src[e]);
        float w = __ldg(&g_wt[e]);
        float4 hs = H4[(size_t)s * F4 + x];
        acc.x += w * hs.x;
        acc.y += w * hs.y;
        acc.z += w * hs.z;
        acc.w += w * hs.w;
    }
    float4 bb = ((const float4*)bias)[x];
    float4 o = make_float4(dv * acc.x + bb.x, dv * acc.y + bb.y,
                           dv * acc.z + bb.z, dv * acc.w + bb.w);
    if (relu) {
        o.x = fmaxf(o.x, 0.f); o.y = fmaxf(o.y, 0.f);
        o.z = fmaxf(o.z, 0.f); o.w = fmaxf(o.w, 0.f);
    }
    ((float4*)Out)[(size_t)v * F4 + x] = o;
}

// ---------------------------------------------------------------------------
// Mean pool by batch id (F=64) + final linear [64 -> 2]
// ---------------------------------------------------------------------------
__global__ void k_pool(const float* __restrict__ Afin, const void* __restrict__ bat,
                       int N) {
    int t = blockIdx.x * blockDim.x + threadIdx.x;
    if (t >= N * 64) return;
    int v = t >> 6, f = t & 63;
    int b = load_idx(bat, v, g_b64);
    atomicAdd(&g_pool[b * 64 + f], Afin[t]);
    if (f == 0) atomicAdd(&g_cnt[b], 1.0f);
}

__global__ void k_final(const float* __restrict__ Wl, const float* __restrict__ bl,
                        float* __restrict__ out, int G) {
    int t = threadIdx.x;
    if (t >= G * 2) return;
    int g = t >> 1, c = t & 1;
    float cnt = fmaxf(g_cnt[g], 1.0f);
    float s = 0.f;
    #pragma unroll
    for (int f = 0; f < 64; f++) s += g_pool[g * 64 + f] * Wl[f * 2 + c];
    out[t] = s / cnt + bl[c];
}

// ---------------------------------------------------------------------------
// Orchestration
// ---------------------------------------------------------------------------
extern "C" void kernel_launch(void* const* d_in, const int* in_sizes, int n_in,
                              void* d_out, int out_size) {
    const float* x  = (const float*)d_in[0];
    const void*  ei = d_in[1];
    const void*  bat = d_in[2];
    const float* W1 = (const float*)d_in[3];
    const float* b1 = (const float*)d_in[4];
    const float* W2 = (const float*)d_in[5];
    const float* b2 = (const float*)d_in[6];
    const float* W3 = (const float*)d_in[7];
    const float* b3 = (const float*)d_in[8];
    const float* Wl = (const float*)d_in[9];
    const float* bl = (const float*)d_in[10];
    float* out = (float*)d_out;

    int N = in_sizes[0] / 512;
    int E = in_sizes[1] / 2;
    int G = out_size / 2;

    void *p_deg, *p_off, *p_cur, *p_bs, *p_bs2, *p_H, *p_A, *p_pool, *p_cnt;
    cudaGetSymbolAddress(&p_deg, g_deg);
    cudaGetSymbolAddress(&p_off, g_off);
    cudaGetSymbolAddress(&p_cur, g_cur);
    cudaGetSymbolAddress(&p_bs, g_bs);
    cudaGetSymbolAddress(&p_bs2, g_bs2);
    cudaGetSymbolAddress(&p_H, g_H);
    cudaGetSymbolAddress(&p_A, g_A);
    cudaGetSymbolAddress(&p_pool, g_pool);
    cudaGetSymbolAddress(&p_cnt, g_cnt);

    // ---- graph preprocessing: deg, dinv, CSR by dst -----------------------
    cudaMemsetAsync(p_deg, 0, N * sizeof(int));
    k_detect<<<1, 256>>>((const unsigned*)ei, (const unsigned*)bat, E, N);
    k_hist<<<(E + 255) / 256, 256>>>(ei, E);
    k_dinv<<<(N + 255) / 256, 256>>>(N);

    int nb = (N + 1023) / 1024;
    k_scan<<<nb, 1024>>>((const int*)p_deg, (int*)p_off, (int*)p_bs, N);
    k_scan<<<1, 1024>>>((const int*)p_bs, (int*)p_bs2, nullptr, nb);
    k_scanadd<<<nb, 1024>>>((int*)p_off, (const int*)p_bs2, N, E);
    cudaMemcpyAsync(p_cur, p_off, N * sizeof(int), cudaMemcpyDeviceToDevice);
    k_scatter<<<(E + 255) / 256, 256>>>(ei, E);

    // ---- layer 1: [N,512]@[512,256], aggregate, relu ----------------------
    {
        dim3 grid((N + GBM - 1) / GBM, 256 / GBN);
        k_gemm<<<grid, 256>>>(x, W1, (float*)p_H, N, 256, 512);
        k_agg<<<(N + 3) / 4, dim3(64, 4)>>>((const float*)p_H, (float*)p_A, b1, N, 1);
    }
    // ---- layer 2: [N,256]@[256,128], aggregate, relu ----------------------
    {
        dim3 grid((N + GBM - 1) / GBM, 128 / GBN);
        k_gemm<<<grid, 256>>>((const float*)p_A, W2, (float*)p_H, N, 128, 256);
        k_agg<<<(N + 7) / 8, dim3(32, 8)>>>((const float*)p_H, (float*)p_A, b2, N, 1);
    }
    // ---- layer 3: [N,128]@[128,64], aggregate (no relu) -------------------
    {
        dim3 grid((N + GBM - 1) / GBM, 64 / GBN);
        k_gemm<<<grid, 256>>>((const float*)p_A, W3, (float*)p_H, N, 64, 128);
        k_agg<<<(N + 15) / 16, dim3(16, 16)>>>((const float*)p_H, (float*)p_A, b3, N, 0);
    }

    // ---- pool + head ------------------------------------------------------
    cudaMemsetAsync(p_pool, 0, G * 64 * sizeof(float));
    cudaMemsetAsync(p_cnt, 0, G * sizeof(float));
    k_pool<<<(N * 64 + 255) / 256, 256>>>((const float*)p_A, bat, N);
    k_final<<<1, 256>>>(Wl, bl, out, G);
}

// round 3
// speedup vs baseline: 2.2281x; 2.2281x over previous
#include <cuda_runtime.h>
#include <cuda_bf16.h>
#include <cstdint>
#include <cstddef>

// ---------------------------------------------------------------------------
// GCN_27874337751415 round 3: HMMA (mma.sync bf16) split-bf16 GEMM.
// tcgen05 unavailable: harness builds via compute_103 (base family) PTX,
// which rejects all 'a'-suffix features. mma.sync.m16n8k16 is baseline.
//   C = Ahi@Bhi + Alo@Bhi + Ahi@Blo  (fp32 accum), err ~2^-16.
// ---------------------------------------------------------------------------

#define MAXN 50176
#define MAXE 800000

__device__ int   g_deg[MAXN];
__device__ float g_dinv[MAXN];
__device__ int   g_off[MAXN + 1];
__device__ int   g_cur[MAXN];
__device__ int   g_bs[1024];
__device__ int   g_bs2[1024];
__device__ int   g_src[MAXE];
__device__ float g_wt[MAXE];
__device__ __align__(16) float g_H[(size_t)MAXN * 256];
__device__ __align__(16) float g_A[(size_t)MAXN * 64];
__device__ __align__(16) __nv_bfloat16 g_Ahi[(size_t)MAXN * 512];
__device__ __align__(16) __nv_bfloat16 g_Alo[(size_t)MAXN * 512];
__device__ __align__(16) __nv_bfloat16 g_Bhi[512 * 256];
__device__ __align__(16) __nv_bfloat16 g_Blo[512 * 256];
__device__ float g_pool[64 * 64];
__device__ float g_cnt[64];
__device__ int   g_ei64;
__device__ int   g_b64;

// ---------------------------------------------------------------------------
// helpers
// ---------------------------------------------------------------------------
__device__ __forceinline__ uint32_t smem_u32(const void* p) {
    uint32_t a;
    asm("{ .reg .u64 t; cvta.to.shared.u64 t, %1; cvt.u32.u64 %0, t; }"
        : "=r"(a) : "l"(p));
    return a;
}
__device__ __forceinline__ void cpa16(uint32_t s, const void* g) {
    asm volatile("cp.async.cg.shared.global [%0], [%1], 16;" :: "r"(s), "l"(g));
}
#define LDM4(r, addr)                                                         \
    asm volatile("ldmatrix.sync.aligned.m8n8.x4.shared.b16 {%0,%1,%2,%3}, [%4];" \
                 : "=r"((r)[0]), "=r"((r)[1]), "=r"((r)[2]), "=r"((r)[3])     \
                 : "r"(addr))
#define MMA16816(c, a, b)                                                     \
    asm volatile("mma.sync.aligned.m16n8k16.row.col.f32.bf16.bf16.f32 "       \
                 "{%0,%1,%2,%3},{%4,%5,%6,%7},{%8,%9},{%0,%1,%2,%3};"         \
                 : "+f"((c)[0]), "+f"((c)[1]), "+f"((c)[2]), "+f"((c)[3])     \
                 : "r"((a)[0]), "r"((a)[1]), "r"((a)[2]), "r"((a)[3]),        \
                   "r"((b)[0]), "r"((b)[1]))

// 64-byte rows, 16B chunks, swizzle chunk by (row>>1)&3 -> ldmatrix conflict-free
__device__ __forceinline__ uint32_t tile_off(int row, int chunk) {
    return (uint32_t)(row * 64 + ((chunk ^ ((row >> 1) & 3)) * 16));
}

// ---------------------------------------------------------------------------
// dtype detection (int64 vs int32 index inputs)
// ---------------------------------------------------------------------------
__global__ void k_detect(const unsigned* __restrict__ ei,
                         const unsigned* __restrict__ bat, int E, int N) {
    __shared__ int s_ei, s_b;
    if (threadIdx.x == 0) { s_ei = 0; s_b = 0; }
    __syncthreads();
    int ne = (E < 1024) ? E : 1024;
    for (int i = threadIdx.x; i < ne; i += blockDim.x)
        if (ei[2 * i + 1]) atomicOr(&s_ei, 1);
    int base = N / 2 - 256; if (base < 0) base = 0;
    int nb2 = (N / 2 > 256) ? 256 : N / 2;
    for (int j = threadIdx.x; j < nb2; j += blockDim.x)
        if (bat[2 * (base + j) + 1]) atomicOr(&s_b, 1);
    __syncthreads();
    if (threadIdx.x == 0) { g_ei64 = s_ei ? 0 : 1; g_b64 = s_b ? 0 : 1; }
}

__device__ __forceinline__ int load_idx(const void* p, int i, int is64) {
    return is64 ? (int)((const long long*)p)[i] : ((const int*)p)[i];
}

// ---------------------------------------------------------------------------
// CSR-by-dst preprocessing
// ---------------------------------------------------------------------------
__global__ void k_hist(const void* __restrict__ ei, int E) {
    int e = blockIdx.x * blockDim.x + threadIdx.x;
    if (e >= E) return;
    atomicAdd(&g_deg[load_idx(ei, E + e, g_ei64)], 1);
}

__global__ void k_dinv(int N) {
    int v = blockIdx.x * blockDim.x + threadIdx.x;
    if (v >= N) return;
    g_dinv[v] = rsqrtf((float)(g_deg[v] + 1));
}

__global__ void k_scan(const int* __restrict__ in, int* __restrict__ out,
                       int* __restrict__ bsum, int n) {
    __shared__ int s[1024];
    int gid = blockIdx.x * 1024 + threadIdx.x;
    int v = (gid < n) ? in[gid] : 0;
    s[threadIdx.x] = v;
    __syncthreads();
    #pragma unroll
    for (int d = 1; d < 1024; d <<= 1) {
        int t = (threadIdx.x >= d) ? s[threadIdx.x - d] : 0;
        __syncthreads();
        s[threadIdx.x] += t;
        __syncthreads();
    }
    if (gid < n) out[gid] = s[threadIdx.x] - v;
    if (bsum != nullptr && threadIdx.x == 1023) bsum[blockIdx.x] = s[1023];
}

__global__ void k_scanadd(int* __restrict__ off, const int* __restrict__ bs2,
                          int n, int E) {
    int gid = blockIdx.x * 1024 + threadIdx.x;
    if (gid < n) off[gid] += bs2[blockIdx.x];
    if (gid == 0) off[n] = E;
}

__global__ void k_scatter(const void* __restrict__ ei, int E) {
    int e = blockIdx.x * blockDim.x + threadIdx.x;
    if (e >= E) return;
    int is64 = g_ei64;
    int s = load_idx(ei, e, is64);
    int d = load_idx(ei, E + e, is64);
    int p = atomicAdd(&g_cur[d], 1);
    g_src[p] = s;
    g_wt[p] = g_dinv[s];
}

// ---------------------------------------------------------------------------
// split-bf16 conversion of x, zero-padded to Mpad rows
// ---------------------------------------------------------------------------
__global__ void k_cvtX(const float* __restrict__ X, __nv_bfloat16* __restrict__ Hi,
                       __nv_bfloat16* __restrict__ Lo, int M, int Mpad, int K) {
    size_t i = ((size_t)blockIdx.x * blockDim.x + threadIdx.x) * 4;
    if (i >= (size_t)Mpad * K) return;
    int row = (int)(i / K);
    float4 v = make_float4(0.f, 0.f, 0.f, 0.f);
    if (row < M) v = *(const float4*)(X + i);
    __nv_bfloat16 h0 = __float2bfloat16(v.x), h1 = __float2bfloat16(v.y);
    __nv_bfloat16 h2 = __float2bfloat16(v.z), h3 = __float2bfloat16(v.w);
    __nv_bfloat16 l0 = __float2bfloat16(v.x - __bfloat162float(h0));
    __nv_bfloat16 l1 = __float2bfloat16(v.y - __bfloat162float(h1));
    __nv_bfloat16 l2 = __float2bfloat16(v.z - __bfloat162float(h2));
    __nv_bfloat16 l3 = __float2bfloat16(v.w - __bfloat162float(h3));
    ((__nv_bfloat162*)(Hi + i))[0] = __halves2bfloat162(h0, h1);
    ((__nv_bfloat162*)(Hi + i))[1] = __halves2bfloat162(h2, h3);
    ((__nv_bfloat162*)(Lo + i))[0] = __halves2bfloat162(l0, l1);
    ((__nv_bfloat162*)(Lo + i))[1] = __halves2bfloat162(l2, l3);
}

// Weight conversion with transpose: W [K x N] fp32 -> Bhi/Blo [N x K] bf16
__global__ void k_cvtB(const float* __restrict__ W, __nv_bfloat16* __restrict__ Hi,
                       __nv_bfloat16* __restrict__ Lo, int K, int N) {
    int t = blockIdx.x * blockDim.x + threadIdx.x;
    if (t >= N * K) return;
    int n = t / K, k = t - n * K;
    float v = W[(size_t)k * N + n];
    __nv_bfloat16 h = __float2bfloat16(v);
    __nv_bfloat16 l = __float2bfloat16(v - __bfloat162float(h));
    Hi[t] = h;
    Lo[t] = l;
}

// ---------------------------------------------------------------------------
// HMMA GEMM: C[M,N] = split-bf16( A[M,K] @ Bt[N,K]^T ), fp32 accum.
// Tile 128x64x32, 256 threads (8 warps = 4x2), warp tile 32x32 via m16n8k16.
// smem per stage: Ahi 8K | Alo 8K | Bhi 4K | Blo 4K = 24K, double-buffered.
// ---------------------------------------------------------------------------
__global__ void __launch_bounds__(256) k_gemm_mma(
    const __nv_bfloat16* __restrict__ Ahi, const __nv_bfloat16* __restrict__ Alo,
    const __nv_bfloat16* __restrict__ Bhi, const __nv_bfloat16* __restrict__ Blo,
    float* __restrict__ C, int M, int N, int K)
{
    extern __shared__ char smem[];
    uint32_t sb = smem_u32(smem);
    int tid = threadIdx.x, lane = tid & 31, wid = tid >> 5;
    int bm = blockIdx.x * 128, bn = blockIdx.y * 64;
    int warp_m = wid & 3, warp_n = wid >> 2;

    float acc[2][4][4];
    #pragma unroll
    for (int i = 0; i < 2; i++)
        #pragma unroll
        for (int j = 0; j < 4; j++)
            #pragma unroll
            for (int q = 0; q < 4; q++) acc[i][j][q] = 0.f;

    const int KC = K >> 5;

    auto load_stage = [&](int it, int s) {
        int k0 = it << 5;
        uint32_t base = sb + s * 24576;
        #pragma unroll
        for (int u = 0; u < 2; u++) {
            int c16 = tid * 2 + u;           // 0..511
            int row = c16 >> 2, ch = c16 & 3;
            uint32_t off = tile_off(row, ch);
            size_t gi = (size_t)(bm + row) * K + k0 + ch * 8;
            cpa16(base + off, Ahi + gi);
            cpa16(base + 8192 + off, Alo + gi);
        }
        {
            int row = tid >> 2, ch = tid & 3;  // 64 rows x 4 chunks
            uint32_t off = tile_off(row, ch);
            size_t gi = (size_t)(bn + row) * K + k0 + ch * 8;
            cpa16(base + 16384 + off, Bhi + gi);
            cpa16(base + 20480 + off, Blo + gi);
        }
        asm volatile("cp.async.commit_group;");
    };

    // per-lane ldmatrix row/chunk components (within a k16 step)
    int a_row = warp_m * 32 + (lane & 15);       // + mt*16
    int a_chi = (lane >> 4);                     // 0/1 -> +16B (k 0-7 / 8-15)
    int blk = lane >> 3;
    int b_row = warp_n * 32 + ((blk >> 1) * 8) + (lane & 7);  // + nt2*16
    int b_chi = (blk & 1);

    load_stage(0, 0);
    for (int it = 0; it < KC; it++) {
        int s = it & 1;
        if (it + 1 < KC) {
            load_stage(it + 1, s ^ 1);
            asm volatile("cp.async.wait_group 1;");
        } else {
            asm volatile("cp.async.wait_group 0;");
        }
        __syncthreads();
        uint32_t base = sb + s * 24576;
        #pragma unroll
        for (int kk = 0; kk < 2; kk++) {
            int ach = kk * 2 + a_chi;   // chunk 0..3 within 64B row
            uint32_t ahi[2][4], alo[2][4], bhi[4][2], blo[4][2];
            #pragma unroll
            for (int mt = 0; mt < 2; mt++) {
                uint32_t off = tile_off(a_row + mt * 16, ach);
                LDM4(ahi[mt], base + off);
                LDM4(alo[mt], base + 8192 + off);
            }
            #pragma unroll
            for (int nt2 = 0; nt2 < 2; nt2++) {
                uint32_t r4[4];
                uint32_t off = tile_off(b_row + nt2 * 16, kk * 2 + b_chi);
                LDM4(r4, base + 16384 + off);
                bhi[nt2 * 2][0] = r4[0]; bhi[nt2 * 2][1] = r4[1];
                bhi[nt2 * 2 + 1][0] = r4[2]; bhi[nt2 * 2 + 1][1] = r4[3];
                LDM4(r4, base + 20480 + off);
                blo[nt2 * 2][0] = r4[0]; blo[nt2 * 2][1] = r4[1];
                blo[nt2 * 2 + 1][0] = r4[2]; blo[nt2 * 2 + 1][1] = r4[3];
            }
            #pragma unroll
            for (int mt = 0; mt < 2; mt++)
                #pragma unroll
                for (int nt = 0; nt < 4; nt++) {
                    MMA16816(acc[mt][nt], ahi[mt], bhi[nt]);
                    MMA16816(acc[mt][nt], alo[mt], bhi[nt]);
                    MMA16816(acc[mt][nt], ahi[mt], blo[nt]);
                }
        }
        __syncthreads();
    }

    // epilogue: c frag lane mapping (row = l>>2 [+8], col = (l&3)*2)
    #pragma unroll
    for (int mt = 0; mt < 2; mt++)
        #pragma unroll
        for (int nt = 0; nt < 4; nt++) {
            int row0 = bm + warp_m * 32 + mt * 16 + (lane >> 2);
            int col = bn + warp_n * 32 + nt * 8 + (lane & 3) * 2;
            if (row0 < M)
                *(float2*)(C + (size_t)row0 * N + col) =
                    make_float2(acc[mt][nt][0], acc[mt][nt][1]);
            if (row0 + 8 < M)
                *(float2*)(C + (size_t)(row0 + 8) * N + col) =
                    make_float2(acc[mt][nt][2], acc[mt][nt][3]);
        }
}

// ---------------------------------------------------------------------------
// Aggregation: Out[v] = dinv[v]*(dinv[v]*H[v] + sum wt*H[src]) + bias
// Optionally writes fp32 and/or split-bf16 hi/lo for the next GEMM.
// ---------------------------------------------------------------------------
__global__ void k_agg(const float* __restrict__ Hin, float* __restrict__ OutF,
                      __nv_bfloat16* __restrict__ OutHi, __nv_bfloat16* __restrict__ OutLo,
                      const float* __restrict__ bias, int N, int Mpad, int relu) {
    int v = blockIdx.x * blockDim.y + threadIdx.y;
    if (v >= Mpad) return;
    int F4 = blockDim.x;
    int x = threadIdx.x;
    int F = F4 * 4;
    if (v >= N) {
        if (OutHi) {
            __nv_bfloat162 z = __halves2bfloat162(__float2bfloat16(0.f), __float2bfloat16(0.f));
            ((__nv_bfloat162*)(OutHi + (size_t)v * F + x * 4))[0] = z;
            ((__nv_bfloat162*)(OutHi + (size_t)v * F + x * 4))[1] = z;
            ((__nv_bfloat162*)(OutLo + (size_t)v * F + x * 4))[0] = z;
            ((__nv_bfloat162*)(OutLo + (size_t)v * F + x * 4))[1] = z;
        }
        return;
    }
    const float4* H4 = (const float4*)Hin;
    float dv = g_dinv[v];
    float4 hv = H4[(size_t)v * F4 + x];
    float4 acc = make_float4(dv * hv.x, dv * hv.y, dv * hv.z, dv * hv.w);
    int e = g_off[v], end = g_off[v + 1];
    for (; e < end; e++) {
        int s = __ldg(&g_src[e]);
        float w = __ldg(&g_wt[e]);
        float4 hs = H4[(size_t)s * F4 + x];
        acc.x += w * hs.x;
        acc.y += w * hs.y;
        acc.z += w * hs.z;
        acc.w += w * hs.w;
    }
    float4 bb = ((const float4*)bias)[x];
    float4 o = make_float4(dv * acc.x + bb.x, dv * acc.y + bb.y,
                           dv * acc.z + bb.z, dv * acc.w + bb.w);
    if (relu) {
        o.x = fmaxf(o.x, 0.f); o.y = fmaxf(o.y, 0.f);
        o.z = fmaxf(o.z, 0.f); o.w = fmaxf(o.w, 0.f);
    }
    if (OutF)
        ((float4*)OutF)[(size_t)v * F4 + x] = o;
    if (OutHi) {
        __nv_bfloat16 h0 = __float2bfloat16(o.x), h1 = __float2bfloat16(o.y);
        __nv_bfloat16 h2 = __float2bfloat16(o.z), h3 = __float2bfloat16(o.w);
        __nv_bfloat16 l0 = __float2bfloat16(o.x - __bfloat162float(h0));
        __nv_bfloat16 l1 = __float2bfloat16(o.y - __bfloat162float(h1));
        __nv_bfloat16 l2 = __float2bfloat16(o.z - __bfloat162float(h2));
        __nv_bfloat16 l3 = __float2bfloat16(o.w - __bfloat162float(h3));
        ((__nv_bfloat162*)(OutHi + (size_t)v * F + x * 4))[0] = __halves2bfloat162(h0, h1);
        ((__nv_bfloat162*)(OutHi + (size_t)v * F + x * 4))[1] = __halves2bfloat162(h2, h3);
        ((__nv_bfloat162*)(OutLo + (size_t)v * F + x * 4))[0] = __halves2bfloat162(l0, l1);
        ((__nv_bfloat162*)(OutLo + (size_t)v * F + x * 4))[1] = __halves2bfloat162(l2, l3);
    }
}

// ---------------------------------------------------------------------------
// Mean pool by batch id (F=64) + final linear [64 -> 2]
// ---------------------------------------------------------------------------
__global__ void k_pool(const float* __restrict__ Afin, const void* __restrict__ bat,
                       int N) {
    int t = blockIdx.x * blockDim.x + threadIdx.x;
    if (t >= N * 64) return;
    int v = t >> 6, f = t & 63;
    int b = load_idx(bat, v, g_b64);
    atomicAdd(&g_pool[b * 64 + f], Afin[t]);
    if (f == 0) atomicAdd(&g_cnt[b], 1.0f);
}

__global__ void k_final(const float* __restrict__ Wl, const float* __restrict__ bl,
                        float* __restrict__ out, int G) {
    int t = threadIdx.x;
    if (t >= G * 2) return;
    int g = t >> 1, c = t & 1;
    float cnt = fmaxf(g_cnt[g], 1.0f);
    float s = 0.f;
    #pragma unroll
    for (int f = 0; f < 64; f++) s += g_pool[g * 64 + f] * Wl[f * 2 + c];
    out[t] = s / cnt + bl[c];
}

// ---------------------------------------------------------------------------
// Orchestration
// ---------------------------------------------------------------------------
extern "C" void kernel_launch(void* const* d_in, const int* in_sizes, int n_in,
                              void* d_out, int out_size) {
    const float* x   = (const float*)d_in[0];
    const void*  ei  = d_in[1];
    const void*  bat = d_in[2];
    const float* W1 = (const float*)d_in[3];
    const float* b1 = (const float*)d_in[4];
    const float* W2 = (const float*)d_in[5];
    const float* b2 = (const float*)d_in[6];
    const float* W3 = (const float*)d_in[7];
    const float* b3 = (const float*)d_in[8];
    const float* Wl = (const float*)d_in[9];
    const float* bl = (const float*)d_in[10];
    float* out = (float*)d_out;

    int N = in_sizes[0] / 512;
    int E = in_sizes[1] / 2;
    int G = out_size / 2;
    int mt = (N + 127) / 128;
    int Mpad = mt * 128;

    static int smem_set = 0;
    if (!smem_set) {
        cudaFuncSetAttribute(k_gemm_mma, cudaFuncAttributeMaxDynamicSharedMemorySize, 49152);
        smem_set = 1;
    }

    void *p_deg, *p_off, *p_cur, *p_bs, *p_bs2, *p_H, *p_A, *p_pool, *p_cnt;
    void *p_Ahi, *p_Alo, *p_Bhi, *p_Blo;
    cudaGetSymbolAddress(&p_deg, g_deg);
    cudaGetSymbolAddress(&p_off, g_off);
    cudaGetSymbolAddress(&p_cur, g_cur);
    cudaGetSymbolAddress(&p_bs, g_bs);
    cudaGetSymbolAddress(&p_bs2, g_bs2);
    cudaGetSymbolAddress(&p_H, g_H);
    cudaGetSymbolAddress(&p_A, g_A);
    cudaGetSymbolAddress(&p_pool, g_pool);
    cudaGetSymbolAddress(&p_cnt, g_cnt);
    cudaGetSymbolAddress(&p_Ahi, g_Ahi);
    cudaGetSymbolAddress(&p_Alo, g_Alo);
    cudaGetSymbolAddress(&p_Bhi, g_Bhi);
    cudaGetSymbolAddress(&p_Blo, g_Blo);

    const __nv_bfloat16* Ahi = (const __nv_bfloat16*)p_Ahi;
    const __nv_bfloat16* Alo = (const __nv_bfloat16*)p_Alo;
    const __nv_bfloat16* Bhi = (const __nv_bfloat16*)p_Bhi;
    const __nv_bfloat16* Blo = (const __nv_bfloat16*)p_Blo;

    // ---- graph preprocessing --------------------------------------------
    cudaMemsetAsync(p_deg, 0, N * sizeof(int));
    k_detect<<<1, 256>>>((const unsigned*)ei, (const unsigned*)bat, E, N);
    k_hist<<<(E + 255) / 256, 256>>>(ei, E);
    k_dinv<<<(N + 255) / 256, 256>>>(N);
    int nb = (N + 1023) / 1024;
    k_scan<<<nb, 1024>>>((const int*)p_deg, (int*)p_off, (int*)p_bs, N);
    k_scan<<<1, 1024>>>((const int*)p_bs, (int*)p_bs2, nullptr, nb);
    k_scanadd<<<nb, 1024>>>((int*)p_off, (const int*)p_bs2, N, E);
    cudaMemcpyAsync(p_cur, p_off, N * sizeof(int), cudaMemcpyDeviceToDevice);
    k_scatter<<<(E + 255) / 256, 256>>>(ei, E);

    // ---- layer 1: x@W1 (K=512,N=256), agg+relu -> split-bf16 ------------
    {
        size_t tot = (size_t)Mpad * 512 / 4;
        k_cvtX<<<(int)((tot + 255) / 256), 256>>>(x, (__nv_bfloat16*)p_Ahi,
                                                  (__nv_bfloat16*)p_Alo, N, Mpad, 512);
        k_cvtB<<<(256 * 512 + 255) / 256, 256>>>(W1, (__nv_bfloat16*)p_Bhi,
                                                 (__nv_bfloat16*)p_Blo, 512, 256);
        k_gemm_mma<<<dim3(mt, 4), 256, 49152>>>(Ahi, Alo, Bhi, Blo, (float*)p_H, N, 256, 512);
        int gb = (Mpad + 3) / 4;
        k_agg<<<gb, dim3(64, 4)>>>((const float*)p_H, nullptr,
                                   (__nv_bfloat16*)p_Ahi, (__nv_bfloat16*)p_Alo,
                                   b1, N, Mpad, 1);
    }
    // ---- layer 2: K=256, N=128 ------------------------------------------
    {
        k_cvtB<<<(128 * 256 + 255) / 256, 256>>>(W2, (__nv_bfloat16*)p_Bhi,
                                                 (__nv_bfloat16*)p_Blo, 256, 128);
        k_gemm_mma<<<dim3(mt, 2), 256, 49152>>>(Ahi, Alo, Bhi, Blo, (float*)p_H, N, 128, 256);
        int gb = (Mpad + 7) / 8;
        k_agg<<<gb, dim3(32, 8)>>>((const float*)p_H, nullptr,
                                   (__nv_bfloat16*)p_Ahi, (__nv_bfloat16*)p_Alo,
                                   b2, N, Mpad, 1);
    }
    // ---- layer 3: K=128, N=64 -------------------------------------------
    {
        k_cvtB<<<(64 * 128 + 255) / 256, 256>>>(W3, (__nv_bfloat16*)p_Bhi,
                                                (__nv_bfloat16*)p_Blo, 128, 64);
        k_gemm_mma<<<dim3(mt, 1), 256, 49152>>>(Ahi, Alo, Bhi, Blo, (float*)p_H, N, 64, 128);
        int gb = (N + 15) / 16;
        k_agg<<<gb, dim3(16, 16)>>>((const float*)p_H, (float*)p_A,
                                    nullptr, nullptr, b3, N, N, 0);
    }

    // ---- pool + head ------------------------------------------------------
    cudaMemsetAsync(p_pool, 0, G * 64 * sizeof(float));
    cudaMemsetAsync(p_cnt, 0, G * sizeof(float));
    k_pool<<<(N * 64 + 255) / 256, 256>>>((const float*)p_A, bat, N);
    k_final<<<1, 256>>>(Wl, bl, out, G);
}

// round 4
// speedup vs baseline: 2.5298x; 1.1354x over previous
#include <cuda_runtime.h>
#include <cuda_bf16.h>
#include <cstdint>
#include <cstddef>

// ---------------------------------------------------------------------------
// GCN_27874337751415 round 4: HMMA split-bf16 GEMM (BN=128 tiles for layers
// 1-2), stream fork-join overlap of CSR preprocessing with layer-1
// convert+GEMM, atomic-free segmented pooling (batch is sorted).
// ---------------------------------------------------------------------------

#define MAXN 50176
#define MAXE 800000

__device__ int   g_deg[MAXN];
__device__ float g_dinv[MAXN];
__device__ int   g_off[MAXN + 1];
__device__ int   g_cur[MAXN];
__device__ int   g_bs[1024];
__device__ int   g_bs2[1024];
__device__ int   g_src[MAXE];
__device__ float g_wt[MAXE];
__device__ __align__(16) float g_H[(size_t)MAXN * 256];
__device__ __align__(16) float g_A[(size_t)MAXN * 64];
__device__ __align__(16) __nv_bfloat16 g_Ahi[(size_t)MAXN * 512];
__device__ __align__(16) __nv_bfloat16 g_Alo[(size_t)MAXN * 512];
__device__ __align__(16) __nv_bfloat16 g_Bhi[512 * 256];
__device__ __align__(16) __nv_bfloat16 g_Blo[512 * 256];
__device__ float g_pool[64 * 64];
__device__ float g_cnt[64];
__device__ int   g_ei64;
__device__ int   g_b64;

// ---------------------------------------------------------------------------
// helpers
// ---------------------------------------------------------------------------
__device__ __forceinline__ uint32_t smem_u32(const void* p) {
    uint32_t a;
    asm("{ .reg .u64 t; cvta.to.shared.u64 t, %1; cvt.u32.u64 %0, t; }"
        : "=r"(a) : "l"(p));
    return a;
}
__device__ __forceinline__ void cpa16(uint32_t s, const void* g) {
    asm volatile("cp.async.cg.shared.global [%0], [%1], 16;" :: "r"(s), "l"(g));
}
#define LDM4(r, addr)                                                         \
    asm volatile("ldmatrix.sync.aligned.m8n8.x4.shared.b16 {%0,%1,%2,%3}, [%4];" \
                 : "=r"((r)[0]), "=r"((r)[1]), "=r"((r)[2]), "=r"((r)[3])     \
                 : "r"(addr))
#define MMA16816(c, a, b)                                                     \
    asm volatile("mma.sync.aligned.m16n8k16.row.col.f32.bf16.bf16.f32 "       \
                 "{%0,%1,%2,%3},{%4,%5,%6,%7},{%8,%9},{%0,%1,%2,%3};"         \
                 : "+f"((c)[0]), "+f"((c)[1]), "+f"((c)[2]), "+f"((c)[3])     \
                 : "r"((a)[0]), "r"((a)[1]), "r"((a)[2]), "r"((a)[3]),        \
                   "r"((b)[0]), "r"((b)[1]))

// 64-byte rows, 16B chunks, swizzle chunk by (row>>1)&3 -> ldmatrix conflict-free
__device__ __forceinline__ uint32_t tile_off(int row, int chunk) {
    return (uint32_t)(row * 64 + ((chunk ^ ((row >> 1) & 3)) * 16));
}

// ---------------------------------------------------------------------------
// dtype detection (int64 vs int32 index inputs)
// ---------------------------------------------------------------------------
__global__ void k_detect(const unsigned* __restrict__ ei,
                         const unsigned* __restrict__ bat, int E, int N) {
    __shared__ int s_ei, s_b;
    if (threadIdx.x == 0) { s_ei = 0; s_b = 0; }
    __syncthreads();
    int ne = (E < 1024) ? E : 1024;
    for (int i = threadIdx.x; i < ne; i += blockDim.x)
        if (ei[2 * i + 1]) atomicOr(&s_ei, 1);
    int base = N / 2 - 256; if (base < 0) base = 0;
    int nb2 = (N / 2 > 256) ? 256 : N / 2;
    for (int j = threadIdx.x; j < nb2; j += blockDim.x)
        if (bat[2 * (base + j) + 1]) atomicOr(&s_b, 1);
    __syncthreads();
    if (threadIdx.x == 0) { g_ei64 = s_ei ? 0 : 1; g_b64 = s_b ? 0 : 1; }
}

__device__ __forceinline__ int load_idx(const void* p, int i, int is64) {
    return is64 ? (int)((const long long*)p)[i] : ((const int*)p)[i];
}

// ---------------------------------------------------------------------------
// CSR-by-dst preprocessing
// ---------------------------------------------------------------------------
__global__ void k_hist(const void* __restrict__ ei, int E) {
    int e = blockIdx.x * blockDim.x + threadIdx.x;
    if (e >= E) return;
    atomicAdd(&g_deg[load_idx(ei, E + e, g_ei64)], 1);
}

__global__ void k_dinv(int N) {
    int v = blockIdx.x * blockDim.x + threadIdx.x;
    if (v >= N) return;
    g_dinv[v] = rsqrtf((float)(g_deg[v] + 1));
}

__global__ void k_scan(const int* __restrict__ in, int* __restrict__ out,
                       int* __restrict__ bsum, int n) {
    __shared__ int s[1024];
    int gid = blockIdx.x * 1024 + threadIdx.x;
    int v = (gid < n) ? in[gid] : 0;
    s[threadIdx.x] = v;
    __syncthreads();
    #pragma unroll
    for (int d = 1; d < 1024; d <<= 1) {
        int t = (threadIdx.x >= d) ? s[threadIdx.x - d] : 0;
        __syncthreads();
        s[threadIdx.x] += t;
        __syncthreads();
    }
    if (gid < n) out[gid] = s[threadIdx.x] - v;
    if (bsum != nullptr && threadIdx.x == 1023) bsum[blockIdx.x] = s[1023];
}

__global__ void k_scanadd(int* __restrict__ off, const int* __restrict__ bs2,
                          int n, int E) {
    int gid = blockIdx.x * 1024 + threadIdx.x;
    if (gid < n) off[gid] += bs2[blockIdx.x];
    if (gid == 0) off[n] = E;
}

__global__ void k_scatter(const void* __restrict__ ei, int E) {
    int e = blockIdx.x * blockDim.x + threadIdx.x;
    if (e >= E) return;
    int is64 = g_ei64;
    int s = load_idx(ei, e, is64);
    int d = load_idx(ei, E + e, is64);
    int p = atomicAdd(&g_cur[d], 1);
    g_src[p] = s;
    g_wt[p] = g_dinv[s];
}

// ---------------------------------------------------------------------------
// split-bf16 conversion of x, zero-padded to Mpad rows
// ---------------------------------------------------------------------------
__global__ void k_cvtX(const float* __restrict__ X, __nv_bfloat16* __restrict__ Hi,
                       __nv_bfloat16* __restrict__ Lo, int M, int Mpad, int K) {
    size_t i = ((size_t)blockIdx.x * blockDim.x + threadIdx.x) * 4;
    if (i >= (size_t)Mpad * K) return;
    int row = (int)(i / K);
    float4 v = make_float4(0.f, 0.f, 0.f, 0.f);
    if (row < M) v = *(const float4*)(X + i);
    __nv_bfloat16 h0 = __float2bfloat16(v.x), h1 = __float2bfloat16(v.y);
    __nv_bfloat16 h2 = __float2bfloat16(v.z), h3 = __float2bfloat16(v.w);
    __nv_bfloat16 l0 = __float2bfloat16(v.x - __bfloat162float(h0));
    __nv_bfloat16 l1 = __float2bfloat16(v.y - __bfloat162float(h1));
    __nv_bfloat16 l2 = __float2bfloat16(v.z - __bfloat162float(h2));
    __nv_bfloat16 l3 = __float2bfloat16(v.w - __bfloat162float(h3));
    ((__nv_bfloat162*)(Hi + i))[0] = __halves2bfloat162(h0, h1);
    ((__nv_bfloat162*)(Hi + i))[1] = __halves2bfloat162(h2, h3);
    ((__nv_bfloat162*)(Lo + i))[0] = __halves2bfloat162(l0, l1);
    ((__nv_bfloat162*)(Lo + i))[1] = __halves2bfloat162(l2, l3);
}

// Weight conversion with transpose: W [K x N] fp32 -> Bhi/Blo [N x K] bf16
__global__ void k_cvtB(const float* __restrict__ W, __nv_bfloat16* __restrict__ Hi,
                       __nv_bfloat16* __restrict__ Lo, int K, int N) {
    int t = blockIdx.x * blockDim.x + threadIdx.x;
    if (t >= N * K) return;
    int n = t / K, k = t - n * K;
    float v = W[(size_t)k * N + n];
    __nv_bfloat16 h = __float2bfloat16(v);
    __nv_bfloat16 l = __float2bfloat16(v - __bfloat162float(h));
    Hi[t] = h;
    Lo[t] = l;
}

// ---------------------------------------------------------------------------
// HMMA GEMM: C[M,N] = split-bf16( A[M,K] @ Bt[N,K]^T ), fp32 accum.
// Tile 128 x BN x 32, 256 threads (8 warps = 4m x 2n), warp tile 32 x (BN/2).
// Per stage: Ahi 8K | Alo 8K | Bhi BN*64 | Blo BN*64, double-buffered.
// ---------------------------------------------------------------------------
template<int BN>
__global__ void __launch_bounds__(256, 1) k_gemm_mma(
    const __nv_bfloat16* __restrict__ Ahi, const __nv_bfloat16* __restrict__ Alo,
    const __nv_bfloat16* __restrict__ Bhi, const __nv_bfloat16* __restrict__ Blo,
    float* __restrict__ C, int M, int N, int K)
{
    constexpr int SS = 16384 + BN * 128;   // stage bytes
    constexpr int NT = BN / 16;            // n8-tiles per warp
    constexpr int WN = BN / 2;             // warp n extent
    extern __shared__ char smem[];
    uint32_t sb = smem_u32(smem);
    int tid = threadIdx.x, lane = tid & 31, wid = tid >> 5;
    int bm = blockIdx.x * 128, bn = blockIdx.y * BN;
    int warp_m = wid & 3, warp_n = wid >> 2;

    float acc[2][NT][4] = {};
    const int KC = K >> 5;

    auto load_stage = [&](int it, int s) {
        int k0 = it << 5;
        uint32_t base = sb + s * SS;
        #pragma unroll
        for (int u = 0; u < 2; u++) {           // A: 512 16B-chunk ids
            int c = tid * 2 + u;
            int row = c >> 2, ch = c & 3;
            uint32_t off = tile_off(row, ch);
            size_t gi = (size_t)(bm + row) * K + k0 + ch * 8;
            cpa16(base + off, Ahi + gi);
            cpa16(base + 8192 + off, Alo + gi);
        }
        #pragma unroll
        for (int u = 0; u < BN / 64; u++) {     // B: BN*4 chunk ids
            int c = tid + u * 256;
            int row = c >> 2, ch = c & 3;
            uint32_t off = tile_off(row, ch);
            size_t gi = (size_t)(bn + row) * K + k0 + ch * 8;
            cpa16(base + 16384 + off, Bhi + gi);
            cpa16(base + 16384 + BN * 64 + off, Blo + gi);
        }
        asm volatile("cp.async.commit_group;");
    };

    int a_row = warp_m * 32 + (lane & 15);
    int a_chi = lane >> 4;
    int blk = lane >> 3;
    int b_rl = ((blk >> 1) * 8) + (lane & 7);
    int b_chi = blk & 1;

    load_stage(0, 0);
    for (int it = 0; it < KC; it++) {
        int s = it & 1;
        if (it + 1 < KC) {
            load_stage(it + 1, s ^ 1);
            asm volatile("cp.async.wait_group 1;");
        } else {
            asm volatile("cp.async.wait_group 0;");
        }
        __syncthreads();
        uint32_t base = sb + s * SS;
        #pragma unroll
        for (int kk = 0; kk < 2; kk++) {
            uint32_t ahi[2][4], alo[2][4];
            int ach = kk * 2 + a_chi;
            #pragma unroll
            for (int mt = 0; mt < 2; mt++) {
                uint32_t off = tile_off(a_row + mt * 16, ach);
                LDM4(ahi[mt], base + off);
                LDM4(alo[mt], base + 8192 + off);
            }
            #pragma unroll
            for (int h = 0; h < NT / 4; h++) {
                uint32_t bhi[4][2], blo[4][2];
                #pragma unroll
                for (int nt2 = 0; nt2 < 2; nt2++) {
                    uint32_t r4[4];
                    int brow = warp_n * WN + h * 32 + nt2 * 16 + b_rl;
                    uint32_t off = tile_off(brow, kk * 2 + b_chi);
                    LDM4(r4, base + 16384 + off);
                    bhi[nt2 * 2][0] = r4[0]; bhi[nt2 * 2][1] = r4[1];
                    bhi[nt2 * 2 + 1][0] = r4[2]; bhi[nt2 * 2 + 1][1] = r4[3];
                    LDM4(r4, base + 16384 + BN * 64 + off);
                    blo[nt2 * 2][0] = r4[0]; blo[nt2 * 2][1] = r4[1];
                    blo[nt2 * 2 + 1][0] = r4[2]; blo[nt2 * 2 + 1][1] = r4[3];
                }
                #pragma unroll
                for (int mt = 0; mt < 2; mt++)
                    #pragma unroll
                    for (int j = 0; j < 4; j++) {
                        MMA16816(acc[mt][h * 4 + j], ahi[mt], bhi[j]);
                        MMA16816(acc[mt][h * 4 + j], alo[mt], bhi[j]);
                        MMA16816(acc[mt][h * 4 + j], ahi[mt], blo[j]);
                    }
            }
        }
        __syncthreads();
    }

    #pragma unroll
    for (int mt = 0; mt < 2; mt++)
        #pragma unroll
        for (int nt = 0; nt < NT; nt++) {
            int row0 = bm + warp_m * 32 + mt * 16 + (lane >> 2);
            int col = bn + warp_n * WN + nt * 8 + (lane & 3) * 2;
            if (row0 < M)
                *(float2*)(C + (size_t)row0 * N + col) =
                    make_float2(acc[mt][nt][0], acc[mt][nt][1]);
            if (row0 + 8 < M)
                *(float2*)(C + (size_t)(row0 + 8) * N + col) =
                    make_float2(acc[mt][nt][2], acc[mt][nt][3]);
        }
}

// ---------------------------------------------------------------------------
// Aggregation: Out[v] = dinv[v]*(dinv[v]*H[v] + sum wt*H[src]) + bias
// ---------------------------------------------------------------------------
__global__ void k_agg(const float* __restrict__ Hin, float* __restrict__ OutF,
                      __nv_bfloat16* __restrict__ OutHi, __nv_bfloat16* __restrict__ OutLo,
                      const float* __restrict__ bias, int N, int Mpad, int relu) {
    int v = blockIdx.x * blockDim.y + threadIdx.y;
    if (v >= Mpad) return;
    int F4 = blockDim.x;
    int x = threadIdx.x;
    int F = F4 * 4;
    if (v >= N) {
        if (OutHi) {
            __nv_bfloat162 z = __halves2bfloat162(__float2bfloat16(0.f), __float2bfloat16(0.f));
            ((__nv_bfloat162*)(OutHi + (size_t)v * F + x * 4))[0] = z;
            ((__nv_bfloat162*)(OutHi + (size_t)v * F + x * 4))[1] = z;
            ((__nv_bfloat162*)(OutLo + (size_t)v * F + x * 4))[0] = z;
            ((__nv_bfloat162*)(OutLo + (size_t)v * F + x * 4))[1] = z;
        }
        return;
    }
    const float4* H4 = (const float4*)Hin;
    float dv = g_dinv[v];
    float4 hv = H4[(size_t)v * F4 + x];
    float4 acc = make_float4(dv * hv.x, dv * hv.y, dv * hv.z, dv * hv.w);
    int e = g_off[v], end = g_off[v + 1];
    for (; e < end; e++) {
        int s = __ldg(&g_src[e]);
        float w = __ldg(&g_wt[e]);
        float4 hs = H4[(size_t)s * F4 + x];
        acc.x += w * hs.x;
        acc.y += w * hs.y;
        acc.z += w * hs.z;
        acc.w += w * hs.w;
    }
    float4 bb = ((const float4*)bias)[x];
    float4 o = make_float4(dv * acc.x + bb.x, dv * acc.y + bb.y,
                           dv * acc.z + bb.z, dv * acc.w + bb.w);
    if (relu) {
        o.x = fmaxf(o.x, 0.f); o.y = fmaxf(o.y, 0.f);
        o.z = fmaxf(o.z, 0.f); o.w = fmaxf(o.w, 0.f);
    }
    if (OutF)
        ((float4*)OutF)[(size_t)v * F4 + x] = o;
    if (OutHi) {
        __nv_bfloat16 h0 = __float2bfloat16(o.x), h1 = __float2bfloat16(o.y);
        __nv_bfloat16 h2 = __float2bfloat16(o.z), h3 = __float2bfloat16(o.w);
        __nv_bfloat16 l0 = __float2bfloat16(o.x - __bfloat162float(h0));
        __nv_bfloat16 l1 = __float2bfloat16(o.y - __bfloat162float(h1));
        __nv_bfloat16 l2 = __float2bfloat16(o.z - __bfloat162float(h2));
        __nv_bfloat16 l3 = __float2bfloat16(o.w - __bfloat162float(h3));
        ((__nv_bfloat162*)(OutHi + (size_t)v * F + x * 4))[0] = __halves2bfloat162(h0, h1);
        ((__nv_bfloat162*)(OutHi + (size_t)v * F + x * 4))[1] = __halves2bfloat162(h2, h3);
        ((__nv_bfloat162*)(OutLo + (size_t)v * F + x * 4))[0] = __halves2bfloat162(l0, l1);
        ((__nv_bfloat162*)(OutLo + (size_t)v * F + x * 4))[1] = __halves2bfloat162(l2, l3);
    }
}

// ---------------------------------------------------------------------------
// Atomic-free pooling: batch is sorted, one block per graph, binary search
// the node range, segmented sum over F=64 features.
// ---------------------------------------------------------------------------
__global__ void k_pool2(const float* __restrict__ Afin, const void* __restrict__ bat,
                        int N) {
    int g = blockIdx.x;
    int t = threadIdx.x;         // 256 threads: 4 node-segments x 64 feats
    int is64 = g_b64;
    int lo = 0, hi = N;
    while (lo < hi) { int m = (lo + hi) >> 1; if (load_idx(bat, m, is64) < g) lo = m + 1; else hi = m; }
    int lo2 = lo, hi2 = N;
    while (lo2 < hi2) { int m = (lo2 + hi2) >> 1; if (load_idx(bat, m, is64) < g + 1) lo2 = m + 1; else hi2 = m; }
    int f = t & 63, seg = t >> 6;
    float acc = 0.f;
    for (int v = lo + seg; v < lo2; v += 4)
        acc += Afin[(size_t)v * 64 + f];
    __shared__ float sm[256];
    sm[t] = acc;
    __syncthreads();
    if (t < 64) {
        float s = sm[t] + sm[t + 64] + sm[t + 128] + sm[t + 192];
        g_pool[g * 64 + t] = s;
        if (t == 0) g_cnt[g] = (float)(lo2 - lo);
    }
}

__global__ void k_final(const float* __restrict__ Wl, const float* __restrict__ bl,
                        float* __restrict__ out, int G) {
    int t = threadIdx.x;
    if (t >= G * 2) return;
    int g = t >> 1, c = t & 1;
    float cnt = fmaxf(g_cnt[g], 1.0f);
    float s = 0.f;
    #pragma unroll
    for (int f = 0; f < 64; f++) s += g_pool[g * 64 + f] * Wl[f * 2 + c];
    out[t] = s / cnt + bl[c];
}

// ---------------------------------------------------------------------------
// Orchestration: fork preprocessing to a side stream, overlap with layer-1
// convert + GEMM, join before the first aggregation.
// ---------------------------------------------------------------------------
extern "C" void kernel_launch(void* const* d_in, const int* in_sizes, int n_in,
                              void* d_out, int out_size) {
    const float* x   = (const float*)d_in[0];
    const void*  ei  = d_in[1];
    const void*  bat = d_in[2];
    const float* W1 = (const float*)d_in[3];
    const float* b1 = (const float*)d_in[4];
    const float* W2 = (const float*)d_in[5];
    const float* b2 = (const float*)d_in[6];
    const float* W3 = (const float*)d_in[7];
    const float* b3 = (const float*)d_in[8];
    const float* Wl = (const float*)d_in[9];
    const float* bl = (const float*)d_in[10];
    float* out = (float*)d_out;

    int N = in_sizes[0] / 512;
    int E = in_sizes[1] / 2;
    int G = out_size / 2;
    int mt = (N + 127) / 128;
    int Mpad = mt * 128;

    static int inited = 0;
    static cudaStream_t s2;
    static cudaEvent_t ev1, ev2;
    if (!inited) {
        cudaFuncSetAttribute(k_gemm_mma<128>, cudaFuncAttributeMaxDynamicSharedMemorySize, 65536);
        cudaFuncSetAttribute(k_gemm_mma<64>, cudaFuncAttributeMaxDynamicSharedMemorySize, 49152);
        cudaStreamCreateWithFlags(&s2, cudaStreamNonBlocking);
        cudaEventCreateWithFlags(&ev1, cudaEventDisableTiming);
        cudaEventCreateWithFlags(&ev2, cudaEventDisableTiming);
        inited = 1;
    }

    void *p_deg, *p_off, *p_cur, *p_bs, *p_bs2, *p_H, *p_A;
    void *p_Ahi, *p_Alo, *p_Bhi, *p_Blo;
    cudaGetSymbolAddress(&p_deg, g_deg);
    cudaGetSymbolAddress(&p_off, g_off);
    cudaGetSymbolAddress(&p_cur, g_cur);
    cudaGetSymbolAddress(&p_bs, g_bs);
    cudaGetSymbolAddress(&p_bs2, g_bs2);
    cudaGetSymbolAddress(&p_H, g_H);
    cudaGetSymbolAddress(&p_A, g_A);
    cudaGetSymbolAddress(&p_Ahi, g_Ahi);
    cudaGetSymbolAddress(&p_Alo, g_Alo);
    cudaGetSymbolAddress(&p_Bhi, g_Bhi);
    cudaGetSymbolAddress(&p_Blo, g_Blo);

    const __nv_bfloat16* Ahi = (const __nv_bfloat16*)p_Ahi;
    const __nv_bfloat16* Alo = (const __nv_bfloat16*)p_Alo;
    const __nv_bfloat16* Bhi = (const __nv_bfloat16*)p_Bhi;
    const __nv_bfloat16* Blo = (const __nv_bfloat16*)p_Blo;

    // ---- fork: CSR preprocessing on side stream -------------------------
    cudaEventRecord(ev1, 0);
    cudaStreamWaitEvent(s2, ev1, 0);
    cudaMemsetAsync(p_deg, 0, N * sizeof(int), s2);
    k_detect<<<1, 256, 0, s2>>>((const unsigned*)ei, (const unsigned*)bat, E, N);
    k_hist<<<(E + 255) / 256, 256, 0, s2>>>(ei, E);
    k_dinv<<<(N + 255) / 256, 256, 0, s2>>>(N);
    int nb = (N + 1023) / 1024;
    k_scan<<<nb, 1024, 0, s2>>>((const int*)p_deg, (int*)p_off, (int*)p_bs, N);
    k_scan<<<1, 1024, 0, s2>>>((const int*)p_bs, (int*)p_bs2, nullptr, nb);
    k_scanadd<<<nb, 1024, 0, s2>>>((int*)p_off, (const int*)p_bs2, N, E);
    cudaMemcpyAsync(p_cur, p_off, N * sizeof(int), cudaMemcpyDeviceToDevice, s2);
    k_scatter<<<(E + 255) / 256, 256, 0, s2>>>(ei, E);
    cudaEventRecord(ev2, s2);

    // ---- main: layer-1 convert + GEMM (independent of CSR) --------------
    {
        size_t tot = (size_t)Mpad * 512 / 4;
        k_cvtX<<<(int)((tot + 255) / 256), 256>>>(x, (__nv_bfloat16*)p_Ahi,
                                                  (__nv_bfloat16*)p_Alo, N, Mpad, 512);
        k_cvtB<<<(256 * 512 + 255) / 256, 256>>>(W1, (__nv_bfloat16*)p_Bhi,
                                                 (__nv_bfloat16*)p_Blo, 512, 256);
        k_gemm_mma<128><<<dim3(mt, 2), 256, 65536>>>(Ahi, Alo, Bhi, Blo,
                                                     (float*)p_H, N, 256, 512);
    }
    // ---- join: aggregation needs CSR ------------------------------------
    cudaStreamWaitEvent(0, ev2, 0);
    {
        int gb = (Mpad + 3) / 4;
        k_agg<<<gb, dim3(64, 4)>>>((const float*)p_H, nullptr,
                                   (__nv_bfloat16*)p_Ahi, (__nv_bfloat16*)p_Alo,
                                   b1, N, Mpad, 1);
    }
    // ---- layer 2: K=256, N=128 ------------------------------------------
    {
        k_cvtB<<<(128 * 256 + 255) / 256, 256>>>(W2, (__nv_bfloat16*)p_Bhi,
                                                 (__nv_bfloat16*)p_Blo, 256, 128);
        k_gemm_mma<128><<<dim3(mt, 1), 256, 65536>>>(Ahi, Alo, Bhi, Blo,
                                                     (float*)p_H, N, 128, 256);
        int gb = (Mpad + 7) / 8;
        k_agg<<<gb, dim3(32, 8)>>>((const float*)p_H, nullptr,
                                   (__nv_bfloat16*)p_Ahi, (__nv_bfloat16*)p_Alo,
                                   b2, N, Mpad, 1);
    }
    // ---- layer 3: K=128, N=64 -------------------------------------------
    {
        k_cvtB<<<(64 * 128 + 255) / 256, 256>>>(W3, (__nv_bfloat16*)p_Bhi,
                                                (__nv_bfloat16*)p_Blo, 128, 64);
        k_gemm_mma<64><<<dim3(mt, 1), 256, 49152>>>(Ahi, Alo, Bhi, Blo,
                                                    (float*)p_H, N, 64, 128);
        int gb = (N + 15) / 16;
        k_agg<<<gb, dim3(16, 16)>>>((const float*)p_H, (float*)p_A,
                                    nullptr, nullptr, b3, N, N, 0);
    }

    // ---- pool + head ------------------------------------------------------
    k_pool2<<<G, 256>>>((const float*)p_A, bat, N);
    k_final<<<1, 256>>>(Wl, bl, out, G);
}

// round 5
// speedup vs baseline: 3.1578x; 1.2482x over previous
#include <cuda_runtime.h>
#include <cuda_fp16.h>
#include <cstdint>
#include <cstddef>

// ---------------------------------------------------------------------------
// GCN_27874337751415 round 5: fp16 2-term GEMM (A split-fp16, B single fp16),
// fp16 H storage to halve aggregation gather traffic. rel_err budget ~2e-4.
// ---------------------------------------------------------------------------

#define MAXN 50176
#define MAXE 800000

__device__ int   g_deg[MAXN];
__device__ float g_dinv[MAXN];
__device__ int   g_off[MAXN + 1];
__device__ int   g_cur[MAXN];
__device__ int   g_bs[1024];
__device__ int   g_bs2[1024];
__device__ int   g_src[MAXE];
__device__ float g_wt[MAXE];
__device__ __align__(16) __half g_H[(size_t)MAXN * 256];     // GEMM out, fp16
__device__ __align__(16) float  g_A[(size_t)MAXN * 64];      // layer-3 agg out
__device__ __align__(16) __half g_Ahi[(size_t)MAXN * 512];
__device__ __align__(16) __half g_Alo[(size_t)MAXN * 512];
__device__ __align__(16) __half g_B[512 * 256];
__device__ float g_pool[64 * 64];
__device__ float g_cnt[64];
__device__ int   g_ei64;
__device__ int   g_b64;

// ---------------------------------------------------------------------------
// helpers
// ---------------------------------------------------------------------------
__device__ __forceinline__ uint32_t smem_u32(const void* p) {
    uint32_t a;
    asm("{ .reg .u64 t; cvta.to.shared.u64 t, %1; cvt.u32.u64 %0, t; }"
        : "=r"(a) : "l"(p));
    return a;
}
__device__ __forceinline__ void cpa16(uint32_t s, const void* g) {
    asm volatile("cp.async.cg.shared.global [%0], [%1], 16;" :: "r"(s), "l"(g));
}
#define LDM4(r, addr)                                                         \
    asm volatile("ldmatrix.sync.aligned.m8n8.x4.shared.b16 {%0,%1,%2,%3}, [%4];" \
                 : "=r"((r)[0]), "=r"((r)[1]), "=r"((r)[2]), "=r"((r)[3])     \
                 : "r"(addr))
#define MMAF16(c, a, b)                                                       \
    asm volatile("mma.sync.aligned.m16n8k16.row.col.f32.f16.f16.f32 "         \
                 "{%0,%1,%2,%3},{%4,%5,%6,%7},{%8,%9},{%0,%1,%2,%3};"         \
                 : "+f"((c)[0]), "+f"((c)[1]), "+f"((c)[2]), "+f"((c)[3])     \
                 : "r"((a)[0]), "r"((a)[1]), "r"((a)[2]), "r"((a)[3]),        \
                   "r"((b)[0]), "r"((b)[1]))

// 64-byte rows, 16B chunks, chunk ^= (row>>1)&3 -> ldmatrix conflict-free
__device__ __forceinline__ uint32_t tile_off(int row, int chunk) {
    return (uint32_t)(row * 64 + ((chunk ^ ((row >> 1) & 3)) * 16));
}

// ---------------------------------------------------------------------------
// dtype detection (int64 vs int32 index inputs)
// ---------------------------------------------------------------------------
__global__ void k_detect(const unsigned* __restrict__ ei,
                         const unsigned* __restrict__ bat, int E, int N) {
    __shared__ int s_ei, s_b;
    if (threadIdx.x == 0) { s_ei = 0; s_b = 0; }
    __syncthreads();
    int ne = (E < 1024) ? E : 1024;
    for (int i = threadIdx.x; i < ne; i += blockDim.x)
        if (ei[2 * i + 1]) atomicOr(&s_ei, 1);
    int base = N / 2 - 256; if (base < 0) base = 0;
    int nb2 = (N / 2 > 256) ? 256 : N / 2;
    for (int j = threadIdx.x; j < nb2; j += blockDim.x)
        if (bat[2 * (base + j) + 1]) atomicOr(&s_b, 1);
    __syncthreads();
    if (threadIdx.x == 0) { g_ei64 = s_ei ? 0 : 1; g_b64 = s_b ? 0 : 1; }
}

__device__ __forceinline__ int load_idx(const void* p, int i, int is64) {
    return is64 ? (int)((const long long*)p)[i] : ((const int*)p)[i];
}

// ---------------------------------------------------------------------------
// CSR-by-dst preprocessing
// ---------------------------------------------------------------------------
__global__ void k_hist(const void* __restrict__ ei, int E) {
    int e = blockIdx.x * blockDim.x + threadIdx.x;
    if (e >= E) return;
    atomicAdd(&g_deg[load_idx(ei, E + e, g_ei64)], 1);
}

__global__ void k_dinv(int N) {
    int v = blockIdx.x * blockDim.x + threadIdx.x;
    if (v >= N) return;
    g_dinv[v] = rsqrtf((float)(g_deg[v] + 1));
}

__global__ void k_scan(const int* __restrict__ in, int* __restrict__ out,
                       int* __restrict__ bsum, int n) {
    __shared__ int s[1024];
    int gid = blockIdx.x * 1024 + threadIdx.x;
    int v = (gid < n) ? in[gid] : 0;
    s[threadIdx.x] = v;
    __syncthreads();
    #pragma unroll
    for (int d = 1; d < 1024; d <<= 1) {
        int t = (threadIdx.x >= d) ? s[threadIdx.x - d] : 0;
        __syncthreads();
        s[threadIdx.x] += t;
        __syncthreads();
    }
    if (gid < n) out[gid] = s[threadIdx.x] - v;
    if (bsum != nullptr && threadIdx.x == 1023) bsum[blockIdx.x] = s[1023];
}

__global__ void k_scanadd(int* __restrict__ off, const int* __restrict__ bs2,
                          int n, int E) {
    int gid = blockIdx.x * 1024 + threadIdx.x;
    if (gid < n) off[gid] += bs2[blockIdx.x];
    if (gid == 0) off[n] = E;
}

__global__ void k_scatter(const void* __restrict__ ei, int E) {
    int e = blockIdx.x * blockDim.x + threadIdx.x;
    if (e >= E) return;
    int is64 = g_ei64;
    int s = load_idx(ei, e, is64);
    int d = load_idx(ei, E + e, is64);
    int p = atomicAdd(&g_cur[d], 1);
    g_src[p] = s;
    g_wt[p] = g_dinv[s];
}

// ---------------------------------------------------------------------------
// split-fp16 conversion of x, zero-padded to Mpad rows
// ---------------------------------------------------------------------------
__global__ void k_cvtX(const float* __restrict__ X, __half* __restrict__ Hi,
                       __half* __restrict__ Lo, int M, int Mpad, int K) {
    size_t i = ((size_t)blockIdx.x * blockDim.x + threadIdx.x) * 4;
    if (i >= (size_t)Mpad * K) return;
    int row = (int)(i / K);
    float4 v = make_float4(0.f, 0.f, 0.f, 0.f);
    if (row < M) v = *(const float4*)(X + i);
    __half h0 = __float2half_rn(v.x), h1 = __float2half_rn(v.y);
    __half h2 = __float2half_rn(v.z), h3 = __float2half_rn(v.w);
    __half l0 = __float2half_rn(v.x - __half2float(h0));
    __half l1 = __float2half_rn(v.y - __half2float(h1));
    __half l2 = __float2half_rn(v.z - __half2float(h2));
    __half l3 = __float2half_rn(v.w - __half2float(h3));
    ((__half2*)(Hi + i))[0] = __halves2half2(h0, h1);
    ((__half2*)(Hi + i))[1] = __halves2half2(h2, h3);
    ((__half2*)(Lo + i))[0] = __halves2half2(l0, l1);
    ((__half2*)(Lo + i))[1] = __halves2half2(l2, l3);
}

// Weight conversion with transpose: W [K x N] fp32 -> B [N x K] fp16
__global__ void k_cvtB(const float* __restrict__ W, __half* __restrict__ Bo,
                       int K, int N) {
    int t = blockIdx.x * blockDim.x + threadIdx.x;
    if (t >= N * K) return;
    int n = t / K, k = t - n * K;
    Bo[t] = __float2half_rn(W[(size_t)k * N + n]);
}

// ---------------------------------------------------------------------------
// HMMA GEMM: C[M,N] = (Ahi + Alo)[M,K] @ B[N,K]^T, fp32 accum, fp16 out.
// Tile 128 x BN x 32, 256 threads (8 warps = 4m x 2n), warp tile 32 x (BN/2).
// Per stage: Ahi 8K | Alo 8K | B BN*64B, double-buffered.
// ---------------------------------------------------------------------------
template<int BN>
__global__ void __launch_bounds__(256, 1) k_gemm_mma(
    const __half* __restrict__ Ahi, const __half* __restrict__ Alo,
    const __half* __restrict__ B, __half* __restrict__ C,
    int M, int N, int K)
{
    constexpr int SS = 16384 + BN * 64;    // stage bytes
    constexpr int NT = BN / 16;            // n8-tiles per warp
    constexpr int WN = BN / 2;             // warp n extent
    extern __shared__ char smem[];
    uint32_t sb = smem_u32(smem);
    int tid = threadIdx.x, lane = tid & 31, wid = tid >> 5;
    int bm = blockIdx.x * 128, bn = blockIdx.y * BN;
    int warp_m = wid & 3, warp_n = wid >> 2;

    float acc[2][NT][4] = {};
    const int KC = K >> 5;

    auto load_stage = [&](int it, int s) {
        int k0 = it << 5;
        uint32_t base = sb + s * SS;
        #pragma unroll
        for (int u = 0; u < 2; u++) {           // A: 512 16B-chunk ids
            int c = tid * 2 + u;
            int row = c >> 2, ch = c & 3;
            uint32_t off = tile_off(row, ch);
            size_t gi = (size_t)(bm + row) * K + k0 + ch * 8;
            cpa16(base + off, Ahi + gi);
            cpa16(base + 8192 + off, Alo + gi);
        }
        #pragma unroll
        for (int u = 0; u < BN / 64; u++) {     // B: BN*4 chunk ids
            int c = tid + u * 256;
            int row = c >> 2, ch = c & 3;
            uint32_t off = tile_off(row, ch);
            size_t gi = (size_t)(bn + row) * K + k0 + ch * 8;
            cpa16(base + 16384 + off, B + gi);
        }
        asm volatile("cp.async.commit_group;");
    };

    int a_row = warp_m * 32 + (lane & 15);
    int a_chi = lane >> 4;
    int blk = lane >> 3;
    int b_rl = ((blk >> 1) * 8) + (lane & 7);
    int b_chi = blk & 1;

    load_stage(0, 0);
    for (int it = 0; it < KC; it++) {
        int s = it & 1;
        if (it + 1 < KC) {
            load_stage(it + 1, s ^ 1);
            asm volatile("cp.async.wait_group 1;");
        } else {
            asm volatile("cp.async.wait_group 0;");
        }
        __syncthreads();
        uint32_t base = sb + s * SS;
        #pragma unroll
        for (int kk = 0; kk < 2; kk++) {
            uint32_t ahi[2][4], alo[2][4];
            int ach = kk * 2 + a_chi;
            #pragma unroll
            for (int mt = 0; mt < 2; mt++) {
                uint32_t off = tile_off(a_row + mt * 16, ach);
                LDM4(ahi[mt], base + off);
                LDM4(alo[mt], base + 8192 + off);
            }
            #pragma unroll
            for (int h = 0; h < NT / 4; h++) {
                uint32_t bf[4][2];
                #pragma unroll
                for (int nt2 = 0; nt2 < 2; nt2++) {
                    uint32_t r4[4];
                    int brow = warp_n * WN + h * 32 + nt2 * 16 + b_rl;
                    uint32_t off = tile_off(brow, kk * 2 + b_chi);
                    LDM4(r4, base + 16384 + off);
                    bf[nt2 * 2][0] = r4[0]; bf[nt2 * 2][1] = r4[1];
                    bf[nt2 * 2 + 1][0] = r4[2]; bf[nt2 * 2 + 1][1] = r4[3];
                }
                #pragma unroll
                for (int mt = 0; mt < 2; mt++)
                    #pragma unroll
                    for (int j = 0; j < 4; j++) {
                        MMAF16(acc[mt][h * 4 + j], ahi[mt], bf[j]);
                        MMAF16(acc[mt][h * 4 + j], alo[mt], bf[j]);
                    }
            }
        }
        __syncthreads();
    }

    #pragma unroll
    for (int mt = 0; mt < 2; mt++)
        #pragma unroll
        for (int nt = 0; nt < NT; nt++) {
            int row0 = bm + warp_m * 32 + mt * 16 + (lane >> 2);
            int col = bn + warp_n * WN + nt * 8 + (lane & 3) * 2;
            if (row0 < M)
                *(__half2*)(C + (size_t)row0 * N + col) =
                    __floats2half2_rn(acc[mt][nt][0], acc[mt][nt][1]);
            if (row0 + 8 < M)
                *(__half2*)(C + (size_t)(row0 + 8) * N + col) =
                    __floats2half2_rn(acc[mt][nt][2], acc[mt][nt][3]);
        }
}

// ---------------------------------------------------------------------------
// Aggregation over fp16 H: Out[v] = dinv[v]*(dinv[v]*H[v] + sum wt*H[src]) + b
// Each thread covers 8 features (one uint4 = 8 halves). fp32 accumulate.
// ---------------------------------------------------------------------------
__global__ void k_agg(const __half* __restrict__ Hin, float* __restrict__ OutF,
                      __half* __restrict__ OutHi, __half* __restrict__ OutLo,
                      const float* __restrict__ bias, int N, int Mpad, int relu) {
    int v = blockIdx.x * blockDim.y + threadIdx.y;
    if (v >= Mpad) return;
    int F8 = blockDim.x;
    int x = threadIdx.x;
    int F = F8 * 8;
    if (v >= N) {
        if (OutHi) {
            uint4 z = make_uint4(0, 0, 0, 0);
            ((uint4*)(OutHi + (size_t)v * F))[x] = z;
            ((uint4*)(OutLo + (size_t)v * F))[x] = z;
        }
        return;
    }
    const uint4* H4 = (const uint4*)Hin;
    float dv = g_dinv[v];
    float acc[8];
    {
        uint4 hv = H4[(size_t)v * F8 + x];
        const __half2* p = (const __half2*)&hv;
        #pragma unroll
        for (int q = 0; q < 4; q++) {
            float2 f = __half22float2(p[q]);
            acc[q * 2] = dv * f.x;
            acc[q * 2 + 1] = dv * f.y;
        }
    }
    int e = g_off[v], end = g_off[v + 1];
    for (; e < end; e++) {
        int s = __ldg(&g_src[e]);
        float w = __ldg(&g_wt[e]);
        uint4 hs = H4[(size_t)s * F8 + x];
        const __half2* p = (const __half2*)&hs;
        #pragma unroll
        for (int q = 0; q < 4; q++) {
            float2 f = __half22float2(p[q]);
            acc[q * 2] += w * f.x;
            acc[q * 2 + 1] += w * f.y;
        }
    }
    float o[8];
    {
        float4 b0 = ((const float4*)bias)[x * 2];
        float4 b1 = ((const float4*)bias)[x * 2 + 1];
        const float* bb = &b0.x;
        o[0] = dv * acc[0] + b0.x; o[1] = dv * acc[1] + b0.y;
        o[2] = dv * acc[2] + b0.z; o[3] = dv * acc[3] + b0.w;
        o[4] = dv * acc[4] + b1.x; o[5] = dv * acc[5] + b1.y;
        o[6] = dv * acc[6] + b1.z; o[7] = dv * acc[7] + b1.w;
        (void)bb;
    }
    if (relu) {
        #pragma unroll
        for (int q = 0; q < 8; q++) o[q] = fmaxf(o[q], 0.f);
    }
    if (OutF) {
        float4* d = (float4*)(OutF + (size_t)v * F + x * 8);
        d[0] = make_float4(o[0], o[1], o[2], o[3]);
        d[1] = make_float4(o[4], o[5], o[6], o[7]);
    }
    if (OutHi) {
        __half2 hi[4], lo[4];
        #pragma unroll
        for (int q = 0; q < 4; q++) {
            __half h0 = __float2half_rn(o[q * 2]);
            __half h1 = __float2half_rn(o[q * 2 + 1]);
            hi[q] = __halves2half2(h0, h1);
            lo[q] = __halves2half2(
                __float2half_rn(o[q * 2] - __half2float(h0)),
                __float2half_rn(o[q * 2 + 1] - __half2float(h1)));
        }
        ((uint4*)(OutHi + (size_t)v * F))[x] = *(uint4*)hi;
        ((uint4*)(OutLo + (size_t)v * F))[x] = *(uint4*)lo;
    }
}

// ---------------------------------------------------------------------------
// Atomic-free pooling: batch sorted; one block per graph; then final linear.
// ---------------------------------------------------------------------------
__global__ void k_pool2(const float* __restrict__ Afin, const void* __restrict__ bat,
                        int N) {
    int g = blockIdx.x;
    int t = threadIdx.x;
    int is64 = g_b64;
    int lo = 0, hi = N;
    while (lo < hi) { int m = (lo + hi) >> 1; if (load_idx(bat, m, is64) < g) lo = m + 1; else hi = m; }
    int lo2 = lo, hi2 = N;
    while (lo2 < hi2) { int m = (lo2 + hi2) >> 1; if (load_idx(bat, m, is64) < g + 1) lo2 = m + 1; else hi2 = m; }
    int f = t & 63, seg = t >> 6;
    float acc = 0.f;
    for (int v = lo + seg; v < lo2; v += 4)
        acc += Afin[(size_t)v * 64 + f];
    __shared__ float sm[256];
    sm[t] = acc;
    __syncthreads();
    if (t < 64) {
        float s = sm[t] + sm[t + 64] + sm[t + 128] + sm[t + 192];
        g_pool[g * 64 + t] = s;
        if (t == 0) g_cnt[g] = (float)(lo2 - lo);
    }
}

__global__ void k_final(const float* __restrict__ Wl, const float* __restrict__ bl,
                        float* __restrict__ out, int G) {
    int t = threadIdx.x;
    if (t >= G * 2) return;
    int g = t >> 1, c = t & 1;
    float cnt = fmaxf(g_cnt[g], 1.0f);
    float s = 0.f;
    #pragma unroll
    for (int f = 0; f < 64; f++) s += g_pool[g * 64 + f] * Wl[f * 2 + c];
    out[t] = s / cnt + bl[c];
}

// ---------------------------------------------------------------------------
// Orchestration: fork preprocessing to a side stream, overlap with layer-1
// convert + GEMM, join before the first aggregation.
// ---------------------------------------------------------------------------
extern "C" void kernel_launch(void* const* d_in, const int* in_sizes, int n_in,
                              void* d_out, int out_size) {
    const float* x   = (const float*)d_in[0];
    const void*  ei  = d_in[1];
    const void*  bat = d_in[2];
    const float* W1 = (const float*)d_in[3];
    const float* b1 = (const float*)d_in[4];
    const float* W2 = (const float*)d_in[5];
    const float* b2 = (const float*)d_in[6];
    const float* W3 = (const float*)d_in[7];
    const float* b3 = (const float*)d_in[8];
    const float* Wl = (const float*)d_in[9];
    const float* bl = (const float*)d_in[10];
    float* out = (float*)d_out;

    int N = in_sizes[0] / 512;
    int E = in_sizes[1] / 2;
    int G = out_size / 2;
    int mt = (N + 127) / 128;
    int Mpad = mt * 128;

    static int inited = 0;
    static cudaStream_t s2;
    static cudaEvent_t ev1, ev2;
    if (!inited) {
        cudaFuncSetAttribute(k_gemm_mma<128>, cudaFuncAttributeMaxDynamicSharedMemorySize, 49152);
        cudaFuncSetAttribute(k_gemm_mma<64>, cudaFuncAttributeMaxDynamicSharedMemorySize, 40960);
        cudaStreamCreateWithFlags(&s2, cudaStreamNonBlocking);
        cudaEventCreateWithFlags(&ev1, cudaEventDisableTiming);
        cudaEventCreateWithFlags(&ev2, cudaEventDisableTiming);
        inited = 1;
    }

    void *p_deg, *p_off, *p_cur, *p_bs, *p_bs2, *p_H, *p_A;
    void *p_Ahi, *p_Alo, *p_B;
    cudaGetSymbolAddress(&p_deg, g_deg);
    cudaGetSymbolAddress(&p_off, g_off);
    cudaGetSymbolAddress(&p_cur, g_cur);
    cudaGetSymbolAddress(&p_bs, g_bs);
    cudaGetSymbolAddress(&p_bs2, g_bs2);
    cudaGetSymbolAddress(&p_H, g_H);
    cudaGetSymbolAddress(&p_A, g_A);
    cudaGetSymbolAddress(&p_Ahi, g_Ahi);
    cudaGetSymbolAddress(&p_Alo, g_Alo);
    cudaGetSymbolAddress(&p_B, g_B);

    const __half* Ahi = (const __half*)p_Ahi;
    const __half* Alo = (const __half*)p_Alo;
    const __half* Bp  = (const __half*)p_B;

    // ---- fork: CSR preprocessing on side stream -------------------------
    cudaEventRecord(ev1, 0);
    cudaStreamWaitEvent(s2, ev1, 0);
    cudaMemsetAsync(p_deg, 0, N * sizeof(int), s2);
    k_detect<<<1, 256, 0, s2>>>((const unsigned*)ei, (const unsigned*)bat, E, N);
    k_hist<<<(E + 255) / 256, 256, 0, s2>>>(ei, E);
    k_dinv<<<(N + 255) / 256, 256, 0, s2>>>(N);
    int nb = (N + 1023) / 1024;
    k_scan<<<nb, 1024, 0, s2>>>((const int*)p_deg, (int*)p_off, (int*)p_bs, N);
    k_scan<<<1, 1024, 0, s2>>>((const int*)p_bs, (int*)p_bs2, nullptr, nb);
    k_scanadd<<<nb, 1024, 0, s2>>>((int*)p_off, (const int*)p_bs2, N, E);
    cudaMemcpyAsync(p_cur, p_off, N * sizeof(int), cudaMemcpyDeviceToDevice, s2);
    k_scatter<<<(E + 255) / 256, 256, 0, s2>>>(ei, E);
    cudaEventRecord(ev2, s2);

    // ---- main: layer-1 convert + GEMM (independent of CSR) --------------
    {
        size_t tot = (size_t)Mpad * 512 / 4;
        k_cvtX<<<(int)((tot + 255) / 256), 256>>>(x, (__half*)p_Ahi,
                                                  (__half*)p_Alo, N, Mpad, 512);
        k_cvtB<<<(256 * 512 + 255) / 256, 256>>>(W1, (__half*)p_B, 512, 256);
        k_gemm_mma<128><<<dim3(mt, 2), 256, 49152>>>(Ahi, Alo, Bp,
                                                     (__half*)p_H, N, 256, 512);
    }
    // ---- join: aggregation needs CSR ------------------------------------
    cudaStreamWaitEvent(0, ev2, 0);
    {
        int gb = (Mpad + 7) / 8;
        k_agg<<<gb, dim3(32, 8)>>>((const __half*)p_H, nullptr,
                                   (__half*)p_Ahi, (__half*)p_Alo, b1, N, Mpad, 1);
    }
    // ---- layer 2: K=256, N=128 ------------------------------------------
    {
        k_cvtB<<<(128 * 256 + 255) / 256, 256>>>(W2, (__half*)p_B, 256, 128);
        k_gemm_mma<128><<<dim3(mt, 1), 256, 49152>>>(Ahi, Alo, Bp,
                                                     (__half*)p_H, N, 128, 256);
        int gb = (Mpad + 15) / 16;
        k_agg<<<gb, dim3(16, 16)>>>((const __half*)p_H, nullptr,
                                    (__half*)p_Ahi, (__half*)p_Alo, b2, N, Mpad, 1);
    }
    // ---- layer 3: K=128, N=64 -------------------------------------------
    {
        k_cvtB<<<(64 * 128 + 255) / 256, 256>>>(W3, (__half*)p_B, 128, 64);
        k_gemm_mma<64><<<dim3(mt, 1), 256, 40960>>>(Ahi, Alo, Bp,
                                                    (__half*)p_H, N, 64, 128);
        int gb = (N + 31) / 32;
        k_agg<<<gb, dim3(8, 32)>>>((const __half*)p_H, (float*)p_A,
                                   nullptr, nullptr, b3, N, N, 0);
    }

    // ---- pool + head ------------------------------------------------------
    k_pool2<<<G, 256>>>((const float*)p_A, bat, N);
    k_final<<<1, 256>>>(Wl, bl, out, G);
}

// round 6
// speedup vs baseline: 3.6424x; 1.1535x over previous
#include <cuda_runtime.h>
#include <cuda_fp16.h>
#include <cstdint>
#include <cstddef>

// ---------------------------------------------------------------------------
// GCN_27874337751415 round 6: single-pass fp16 HMMA GEMM (A and B fp16,
// fp32 accum), fp16 H storage, unrolled gather. rel_err budget ~2e-4.
// ---------------------------------------------------------------------------

#define MAXN 50176
#define MAXE 800000

__device__ int   g_deg[MAXN];
__device__ float g_dinv[MAXN];
__device__ int   g_off[MAXN + 1];
__device__ int   g_cur[MAXN];
__device__ int   g_bs[1024];
__device__ int   g_bs2[1024];
__device__ int   g_src[MAXE];
__device__ float g_wt[MAXE];
__device__ __align__(16) __half g_H[(size_t)MAXN * 256];   // GEMM out, fp16
__device__ __align__(16) float  g_A[(size_t)MAXN * 64];    // layer-3 agg out
__device__ __align__(16) __half g_X[(size_t)MAXN * 512];   // GEMM A input
__device__ __align__(16) __half g_B[512 * 256];
__device__ float g_pool[64 * 64];
__device__ float g_cnt[64];
__device__ int   g_ei64;
__device__ int   g_b64;

// ---------------------------------------------------------------------------
// helpers
// ---------------------------------------------------------------------------
__device__ __forceinline__ uint32_t smem_u32(const void* p) {
    uint32_t a;
    asm("{ .reg .u64 t; cvta.to.shared.u64 t, %1; cvt.u32.u64 %0, t; }"
        : "=r"(a) : "l"(p));
    return a;
}
__device__ __forceinline__ void cpa16(uint32_t s, const void* g) {
    asm volatile("cp.async.cg.shared.global [%0], [%1], 16;" :: "r"(s), "l"(g));
}
#define LDM4(r, addr)                                                         \
    asm volatile("ldmatrix.sync.aligned.m8n8.x4.shared.b16 {%0,%1,%2,%3}, [%4];" \
                 : "=r"((r)[0]), "=r"((r)[1]), "=r"((r)[2]), "=r"((r)[3])     \
                 : "r"(addr))
#define MMAF16(c, a, b)                                                       \
    asm volatile("mma.sync.aligned.m16n8k16.row.col.f32.f16.f16.f32 "         \
                 "{%0,%1,%2,%3},{%4,%5,%6,%7},{%8,%9},{%0,%1,%2,%3};"         \
                 : "+f"((c)[0]), "+f"((c)[1]), "+f"((c)[2]), "+f"((c)[3])     \
                 : "r"((a)[0]), "r"((a)[1]), "r"((a)[2]), "r"((a)[3]),        \
                   "r"((b)[0]), "r"((b)[1]))

// 64-byte rows, 16B chunks, chunk ^= (row>>1)&3 -> ldmatrix conflict-free
__device__ __forceinline__ uint32_t tile_off(int row, int chunk) {
    return (uint32_t)(row * 64 + ((chunk ^ ((row >> 1) & 3)) * 16));
}

// ---------------------------------------------------------------------------
// dtype detection (int64 vs int32 index inputs)
// ---------------------------------------------------------------------------
__global__ void k_detect(const unsigned* __restrict__ ei,
                         const unsigned* __restrict__ bat, int E, int N) {
    __shared__ int s_ei, s_b;
    if (threadIdx.x == 0) { s_ei = 0; s_b = 0; }
    __syncthreads();
    int ne = (E < 1024) ? E : 1024;
    for (int i = threadIdx.x; i < ne; i += blockDim.x)
        if (ei[2 * i + 1]) atomicOr(&s_ei, 1);
    int base = N / 2 - 256; if (base < 0) base = 0;
    int nb2 = (N / 2 > 256) ? 256 : N / 2;
    for (int j = threadIdx.x; j < nb2; j += blockDim.x)
        if (bat[2 * (base + j) + 1]) atomicOr(&s_b, 1);
    __syncthreads();
    if (threadIdx.x == 0) { g_ei64 = s_ei ? 0 : 1; g_b64 = s_b ? 0 : 1; }
}

__device__ __forceinline__ int load_idx(const void* p, int i, int is64) {
    return is64 ? (int)((const long long*)p)[i] : ((const int*)p)[i];
}

// ---------------------------------------------------------------------------
// CSR-by-dst preprocessing
// ---------------------------------------------------------------------------
__global__ void k_hist(const void* __restrict__ ei, int E) {
    int e = blockIdx.x * blockDim.x + threadIdx.x;
    if (e >= E) return;
    atomicAdd(&g_deg[load_idx(ei, E + e, g_ei64)], 1);
}

__global__ void k_dinv(int N) {
    int v = blockIdx.x * blockDim.x + threadIdx.x;
    if (v >= N) return;
    g_dinv[v] = rsqrtf((float)(g_deg[v] + 1));
}

__global__ void k_scan(const int* __restrict__ in, int* __restrict__ out,
                       int* __restrict__ bsum, int n) {
    __shared__ int s[1024];
    int gid = blockIdx.x * 1024 + threadIdx.x;
    int v = (gid < n) ? in[gid] : 0;
    s[threadIdx.x] = v;
    __syncthreads();
    #pragma unroll
    for (int d = 1; d < 1024; d <<= 1) {
        int t = (threadIdx.x >= d) ? s[threadIdx.x - d] : 0;
        __syncthreads();
        s[threadIdx.x] += t;
        __syncthreads();
    }
    if (gid < n) out[gid] = s[threadIdx.x] - v;
    if (bsum != nullptr && threadIdx.x == 1023) bsum[blockIdx.x] = s[1023];
}

__global__ void k_scanadd(int* __restrict__ off, const int* __restrict__ bs2,
                          int n, int E) {
    int gid = blockIdx.x * 1024 + threadIdx.x;
    if (gid < n) off[gid] += bs2[blockIdx.x];
    if (gid == 0) off[n] = E;
}

__global__ void k_scatter(const void* __restrict__ ei, int E) {
    int e = blockIdx.x * blockDim.x + threadIdx.x;
    if (e >= E) return;
    int is64 = g_ei64;
    int s = load_idx(ei, e, is64);
    int d = load_idx(ei, E + e, is64);
    int p = atomicAdd(&g_cur[d], 1);
    g_src[p] = s;
    g_wt[p] = g_dinv[s];
}

// ---------------------------------------------------------------------------
// fp16 conversion of x, zero-padded to Mpad rows
// ---------------------------------------------------------------------------
__global__ void k_cvtX(const float* __restrict__ X, __half* __restrict__ Xo,
                       int M, int Mpad, int K) {
    size_t i = ((size_t)blockIdx.x * blockDim.x + threadIdx.x) * 4;
    if (i >= (size_t)Mpad * K) return;
    int row = (int)(i / K);
    float4 v = make_float4(0.f, 0.f, 0.f, 0.f);
    if (row < M) v = *(const float4*)(X + i);
    ((__half2*)(Xo + i))[0] = __floats2half2_rn(v.x, v.y);
    ((__half2*)(Xo + i))[1] = __floats2half2_rn(v.z, v.w);
}

// Weight conversion with transpose: W [K x N] fp32 -> B [N x K] fp16
__global__ void k_cvtB(const float* __restrict__ W, __half* __restrict__ Bo,
                       int K, int N) {
    int t = blockIdx.x * blockDim.x + threadIdx.x;
    if (t >= N * K) return;
    int n = t / K, k = t - n * K;
    Bo[t] = __float2half_rn(W[(size_t)k * N + n]);
}

// ---------------------------------------------------------------------------
// HMMA GEMM: C[M,N] = A[M,K] @ B[N,K]^T, fp16 in, fp32 accum, fp16 out.
// Tile 128 x BN x 32, 256 threads (8 warps = 4m x 2n), warp tile 32 x (BN/2).
// Per stage: A 8K | B BN*64B, double-buffered.
// ---------------------------------------------------------------------------
template<int BN>
__global__ void __launch_bounds__(256, 1) k_gemm_mma(
    const __half* __restrict__ A, const __half* __restrict__ B,
    __half* __restrict__ C, int M, int N, int K)
{
    constexpr int SS = 8192 + BN * 64;     // stage bytes
    constexpr int NT = BN / 16;            // n8-tiles per warp
    constexpr int WN = BN / 2;             // warp n extent
    extern __shared__ char smem[];
    uint32_t sb = smem_u32(smem);
    int tid = threadIdx.x, lane = tid & 31, wid = tid >> 5;
    int bm = blockIdx.x * 128, bn = blockIdx.y * BN;
    int warp_m = wid & 3, warp_n = wid >> 2;

    float acc[2][NT][4] = {};
    const int KC = K >> 5;

    auto load_stage = [&](int it, int s) {
        int k0 = it << 5;
        uint32_t base = sb + s * SS;
        #pragma unroll
        for (int u = 0; u < 2; u++) {           // A: 512 16B-chunk ids
            int c = tid * 2 + u;
            int row = c >> 2, ch = c & 3;
            uint32_t off = tile_off(row, ch);
            cpa16(base + off, A + (size_t)(bm + row) * K + k0 + ch * 8);
        }
        #pragma unroll
        for (int u = 0; u < BN / 64; u++) {     // B: BN*4 chunk ids
            int c = tid + u * 256;
            int row = c >> 2, ch = c & 3;
            uint32_t off = tile_off(row, ch);
            cpa16(base + 8192 + off, B + (size_t)(bn + row) * K + k0 + ch * 8);
        }
        asm volatile("cp.async.commit_group;");
    };

    int a_row = warp_m * 32 + (lane & 15);
    int a_chi = lane >> 4;
    int blk = lane >> 3;
    int b_rl = ((blk >> 1) * 8) + (lane & 7);
    int b_chi = blk & 1;

    load_stage(0, 0);
    for (int it = 0; it < KC; it++) {
        int s = it & 1;
        if (it + 1 < KC) {
            load_stage(it + 1, s ^ 1);
            asm volatile("cp.async.wait_group 1;");
        } else {
            asm volatile("cp.async.wait_group 0;");
        }
        __syncthreads();
        uint32_t base = sb + s * SS;
        #pragma unroll
        for (int kk = 0; kk < 2; kk++) {
            uint32_t af[2][4];
            int ach = kk * 2 + a_chi;
            #pragma unroll
            for (int mt = 0; mt < 2; mt++) {
                uint32_t off = tile_off(a_row + mt * 16, ach);
                LDM4(af[mt], base + off);
            }
            #pragma unroll
            for (int h = 0; h < NT / 4; h++) {
                uint32_t bf[4][2];
                #pragma unroll
                for (int nt2 = 0; nt2 < 2; nt2++) {
                    uint32_t r4[4];
                    int brow = warp_n * WN + h * 32 + nt2 * 16 + b_rl;
                    uint32_t off = tile_off(brow, kk * 2 + b_chi);
                    LDM4(r4, base + 8192 + off);
                    bf[nt2 * 2][0] = r4[0]; bf[nt2 * 2][1] = r4[1];
                    bf[nt2 * 2 + 1][0] = r4[2]; bf[nt2 * 2 + 1][1] = r4[3];
                }
                #pragma unroll
                for (int mt = 0; mt < 2; mt++)
                    #pragma unroll
                    for (int j = 0; j < 4; j++)
                        MMAF16(acc[mt][h * 4 + j], af[mt], bf[j]);
            }
        }
        __syncthreads();
    }

    #pragma unroll
    for (int mt = 0; mt < 2; mt++)
        #pragma unroll
        for (int nt = 0; nt < NT; nt++) {
            int row0 = bm + warp_m * 32 + mt * 16 + (lane >> 2);
            int col = bn + warp_n * WN + nt * 8 + (lane & 3) * 2;
            if (row0 < M)
                *(__half2*)(C + (size_t)row0 * N + col) =
                    __floats2half2_rn(acc[mt][nt][0], acc[mt][nt][1]);
            if (row0 + 8 < M)
                *(__half2*)(C + (size_t)(row0 + 8) * N + col) =
                    __floats2half2_rn(acc[mt][nt][2], acc[mt][nt][3]);
        }
}

// ---------------------------------------------------------------------------
// Aggregation over fp16 H: Out[v] = dinv[v]*(dinv[v]*H[v] + sum wt*H[src]) + b
// Each thread covers 8 features (one uint4 = 8 halves); fp32 accumulate;
// edge loop unrolled x2 for MLP.
// ---------------------------------------------------------------------------
__global__ void k_agg(const __half* __restrict__ Hin, float* __restrict__ OutF,
                      __half* __restrict__ OutH,
                      const float* __restrict__ bias, int N, int Mpad, int relu) {
    int v = blockIdx.x * blockDim.y + threadIdx.y;
    if (v >= Mpad) return;
    int F8 = blockDim.x;
    int x = threadIdx.x;
    int F = F8 * 8;
    if (v >= N) {
        if (OutH)
            ((uint4*)(OutH + (size_t)v * F))[x] = make_uint4(0, 0, 0, 0);
        return;
    }
    const uint4* H4 = (const uint4*)Hin;
    float dv = g_dinv[v];
    float acc[8];
    {
        uint4 hv = H4[(size_t)v * F8 + x];
        const __half2* p = (const __half2*)&hv;
        #pragma unroll
        for (int q = 0; q < 4; q++) {
            float2 f = __half22float2(p[q]);
            acc[q * 2] = dv * f.x;
            acc[q * 2 + 1] = dv * f.y;
        }
    }
    int e = g_off[v], end = g_off[v + 1];
    for (; e + 1 < end; e += 2) {
        int s0 = __ldg(&g_src[e]);
        int s1 = __ldg(&g_src[e + 1]);
        float w0 = __ldg(&g_wt[e]);
        float w1 = __ldg(&g_wt[e + 1]);
        uint4 h0 = H4[(size_t)s0 * F8 + x];
        uint4 h1 = H4[(size_t)s1 * F8 + x];
        const __half2* p0 = (const __half2*)&h0;
        const __half2* p1 = (const __half2*)&h1;
        #pragma unroll
        for (int q = 0; q < 4; q++) {
            float2 f0 = __half22float2(p0[q]);
            float2 f1 = __half22float2(p1[q]);
            acc[q * 2]     += w0 * f0.x + w1 * f1.x;
            acc[q * 2 + 1] += w0 * f0.y + w1 * f1.y;
        }
    }
    if (e < end) {
        int s0 = __ldg(&g_src[e]);
        float w0 = __ldg(&g_wt[e]);
        uint4 h0 = H4[(size_t)s0 * F8 + x];
        const __half2* p0 = (const __half2*)&h0;
        #pragma unroll
        for (int q = 0; q < 4; q++) {
            float2 f0 = __half22float2(p0[q]);
            acc[q * 2]     += w0 * f0.x;
            acc[q * 2 + 1] += w0 * f0.y;
        }
    }
    float o[8];
    {
        float4 b0 = ((const float4*)bias)[x * 2];
        float4 b1 = ((const float4*)bias)[x * 2 + 1];
        o[0] = dv * acc[0] + b0.x; o[1] = dv * acc[1] + b0.y;
        o[2] = dv * acc[2] + b0.z; o[3] = dv * acc[3] + b0.w;
        o[4] = dv * acc[4] + b1.x; o[5] = dv * acc[5] + b1.y;
        o[6] = dv * acc[6] + b1.z; o[7] = dv * acc[7] + b1.w;
    }
    if (relu) {
        #pragma unroll
        for (int q = 0; q < 8; q++) o[q] = fmaxf(o[q], 0.f);
    }
    if (OutF) {
        float4* d = (float4*)(OutF + (size_t)v * F + x * 8);
        d[0] = make_float4(o[0], o[1], o[2], o[3]);
        d[1] = make_float4(o[4], o[5], o[6], o[7]);
    }
    if (OutH) {
        __half2 hh[4];
        #pragma unroll
        for (int q = 0; q < 4; q++)
            hh[q] = __floats2half2_rn(o[q * 2], o[q * 2 + 1]);
        ((uint4*)(OutH + (size_t)v * F))[x] = *(uint4*)hh;
    }
}

// ---------------------------------------------------------------------------
// Atomic-free pooling: batch sorted; one block per graph; then final linear.
// ---------------------------------------------------------------------------
__global__ void k_pool2(const float* __restrict__ Afin, const void* __restrict__ bat,
                        int N) {
    int g = blockIdx.x;
    int t = threadIdx.x;
    int is64 = g_b64;
    int lo = 0, hi = N;
    while (lo < hi) { int m = (lo + hi) >> 1; if (load_idx(bat, m, is64) < g) lo = m + 1; else hi = m; }
    int lo2 = lo, hi2 = N;
    while (lo2 < hi2) { int m = (lo2 + hi2) >> 1; if (load_idx(bat, m, is64) < g + 1) lo2 = m + 1; else hi2 = m; }
    int f = t & 63, seg = t >> 6;
    float acc = 0.f;
    for (int v = lo + seg; v < lo2; v += 4)
        acc += Afin[(size_t)v * 64 + f];
    __shared__ float sm[256];
    sm[t] = acc;
    __syncthreads();
    if (t < 64) {
        float s = sm[t] + sm[t + 64] + sm[t + 128] + sm[t + 192];
        g_pool[g * 64 + t] = s;
        if (t == 0) g_cnt[g] = (float)(lo2 - lo);
    }
}

__global__ void k_final(const float* __restrict__ Wl, const float* __restrict__ bl,
                        float* __restrict__ out, int G) {
    int t = threadIdx.x;
    if (t >= G * 2) return;
    int g = t >> 1, c = t & 1;
    float cnt = fmaxf(g_cnt[g], 1.0f);
    float s = 0.f;
    #pragma unroll
    for (int f = 0; f < 64; f++) s += g_pool[g * 64 + f] * Wl[f * 2 + c];
    out[t] = s / cnt + bl[c];
}

// ---------------------------------------------------------------------------
// Orchestration: fork preprocessing to a side stream, overlap with layer-1
// convert + GEMM, join before the first aggregation.
// ---------------------------------------------------------------------------
extern "C" void kernel_launch(void* const* d_in, const int* in_sizes, int n_in,
                              void* d_out, int out_size) {
    const float* x   = (const float*)d_in[0];
    const void*  ei  = d_in[1];
    const void*  bat = d_in[2];
    const float* W1 = (const float*)d_in[3];
    const float* b1 = (const float*)d_in[4];
    const float* W2 = (const float*)d_in[5];
    const float* b2 = (const float*)d_in[6];
    const float* W3 = (const float*)d_in[7];
    const float* b3 = (const float*)d_in[8];
    const float* Wl = (const float*)d_in[9];
    const float* bl = (const float*)d_in[10];
    float* out = (float*)d_out;

    int N = in_sizes[0] / 512;
    int E = in_sizes[1] / 2;
    int G = out_size / 2;
    int mt = (N + 127) / 128;
    int Mpad = mt * 128;

    static int inited = 0;
    static cudaStream_t s2;
    static cudaEvent_t ev1, ev2;
    if (!inited) {
        cudaFuncSetAttribute(k_gemm_mma<128>, cudaFuncAttributeMaxDynamicSharedMemorySize, 32768);
        cudaFuncSetAttribute(k_gemm_mma<64>, cudaFuncAttributeMaxDynamicSharedMemorySize, 24576);
        cudaStreamCreateWithFlags(&s2, cudaStreamNonBlocking);
        cudaEventCreateWithFlags(&ev1, cudaEventDisableTiming);
        cudaEventCreateWithFlags(&ev2, cudaEventDisableTiming);
        inited = 1;
    }

    void *p_deg, *p_off, *p_cur, *p_bs, *p_bs2, *p_H, *p_A, *p_X, *p_B;
    cudaGetSymbolAddress(&p_deg, g_deg);
    cudaGetSymbolAddress(&p_off, g_off);
    cudaGetSymbolAddress(&p_cur, g_cur);
    cudaGetSymbolAddress(&p_bs, g_bs);
    cudaGetSymbolAddress(&p_bs2, g_bs2);
    cudaGetSymbolAddress(&p_H, g_H);
    cudaGetSymbolAddress(&p_A, g_A);
    cudaGetSymbolAddress(&p_X, g_X);
    cudaGetSymbolAddress(&p_B, g_B);

    const __half* Xp = (const __half*)p_X;
    const __half* Bp = (const __half*)p_B;

    // ---- fork: CSR preprocessing on side stream -------------------------
    cudaEventRecord(ev1, 0);
    cudaStreamWaitEvent(s2, ev1, 0);
    cudaMemsetAsync(p_deg, 0, N * sizeof(int), s2);
    k_detect<<<1, 256, 0, s2>>>((const unsigned*)ei, (const unsigned*)bat, E, N);
    k_hist<<<(E + 255) / 256, 256, 0, s2>>>(ei, E);
    k_dinv<<<(N + 255) / 256, 256, 0, s2>>>(N);
    int nb = (N + 1023) / 1024;
    k_scan<<<nb, 1024, 0, s2>>>((const int*)p_deg, (int*)p_off, (int*)p_bs, N);
    k_scan<<<1, 1024, 0, s2>>>((const int*)p_bs, (int*)p_bs2, nullptr, nb);
    k_scanadd<<<nb, 1024, 0, s2>>>((int*)p_off, (const int*)p_bs2, N, E);
    cudaMemcpyAsync(p_cur, p_off, N * sizeof(int), cudaMemcpyDeviceToDevice, s2);
    k_scatter<<<(E + 255) / 256, 256, 0, s2>>>(ei, E);
    cudaEventRecord(ev2, s2);

    // ---- main: layer-1 convert + GEMM (independent of CSR) --------------
    {
        size_t tot = (size_t)Mpad * 512 / 4;
        k_cvtX<<<(int)((tot + 255) / 256), 256>>>(x, (__half*)p_X, N, Mpad, 512);
        k_cvtB<<<(256 * 512 + 255) / 256, 256>>>(W1, (__half*)p_B, 512, 256);
        k_gemm_mma<128><<<dim3(mt, 2), 256, 32768>>>(Xp, Bp, (__half*)p_H, N, 256, 512);
    }
    // ---- join: aggregation needs CSR ------------------------------------
    cudaStreamWaitEvent(0, ev2, 0);
    {
        int gb = (Mpad + 7) / 8;
        k_agg<<<gb, dim3(32, 8)>>>((const __half*)p_H, nullptr,
                                   (__half*)p_X, b1, N, Mpad, 1);
    }
    // ---- layer 2: K=256, N=128 ------------------------------------------
    {
        k_cvtB<<<(128 * 256 + 255) / 256, 256>>>(W2, (__half*)p_B, 256, 128);
        k_gemm_mma<128><<<dim3(mt, 1), 256, 32768>>>(Xp, Bp, (__half*)p_H, N, 128, 256);
        int gb = (Mpad + 15) / 16;
        k_agg<<<gb, dim3(16, 16)>>>((const __half*)p_H, nullptr,
                                    (__half*)p_X, b2, N, Mpad, 1);
    }
    // ---- layer 3: K=128, N=64 -------------------------------------------
    {
        k_cvtB<<<(64 * 128 + 255) / 256, 256>>>(W3, (__half*)p_B, 128, 64);
        k_gemm_mma<64><<<dim3(mt, 1), 256, 24576>>>(Xp, Bp, (__half*)p_H, N, 64, 128);
        int gb = (N + 31) / 32;
        k_agg<<<gb, dim3(8, 32)>>>((const __half*)p_H, (float*)p_A,
                                   nullptr, b3, N, N, 0);
    }

    // ---- pool + head ------------------------------------------------------
    k_pool2<<<G, 256>>>((const float*)p_A, bat, N);
    k_final<<<1, 256>>>(Wl, bl, out, G);
}

// round 7
// speedup vs baseline: 3.7274x; 1.0233x over previous
#include <cuda_runtime.h>
#include <cuda_fp16.h>
#include <cstdint>
#include <cstddef>

// ---------------------------------------------------------------------------
// GCN_27874337751415 round 7: fp16 HMMA GEMM, fp16 H, launch-count reduction
// (fused weight convert, inline rsqrt, fused pool+head), 4x unrolled gather.
// ---------------------------------------------------------------------------

#define MAXN 50176
#define MAXE 800000

__device__ int   g_deg[MAXN];
__device__ int   g_off[MAXN + 1];
__device__ int   g_cur[MAXN];
__device__ int   g_bs[1024];
__device__ int   g_bs2[1024];
__device__ int   g_src[MAXE];
__device__ float g_wt[MAXE];
__device__ __align__(16) __half g_H[(size_t)MAXN * 256];   // GEMM out, fp16
__device__ __align__(16) float  g_A[(size_t)MAXN * 64];    // layer-3 agg out
__device__ __align__(16) __half g_X[(size_t)MAXN * 512];   // GEMM A input
__device__ __align__(16) __half g_B1[512 * 256];
__device__ __align__(16) __half g_B2[256 * 128];
__device__ __align__(16) __half g_B3[128 * 64];
__device__ int   g_ei64;
__device__ int   g_b64;

// ---------------------------------------------------------------------------
// helpers
// ---------------------------------------------------------------------------
__device__ __forceinline__ uint32_t smem_u32(const void* p) {
    uint32_t a;
    asm("{ .reg .u64 t; cvta.to.shared.u64 t, %1; cvt.u32.u64 %0, t; }"
        : "=r"(a) : "l"(p));
    return a;
}
__device__ __forceinline__ void cpa16(uint32_t s, const void* g) {
    asm volatile("cp.async.cg.shared.global [%0], [%1], 16;" :: "r"(s), "l"(g));
}
#define LDM4(r, addr)                                                         \
    asm volatile("ldmatrix.sync.aligned.m8n8.x4.shared.b16 {%0,%1,%2,%3}, [%4];" \
                 : "=r"((r)[0]), "=r"((r)[1]), "=r"((r)[2]), "=r"((r)[3])     \
                 : "r"(addr))
#define MMAF16(c, a, b)                                                       \
    asm volatile("mma.sync.aligned.m16n8k16.row.col.f32.f16.f16.f32 "         \
                 "{%0,%1,%2,%3},{%4,%5,%6,%7},{%8,%9},{%0,%1,%2,%3};"         \
                 : "+f"((c)[0]), "+f"((c)[1]), "+f"((c)[2]), "+f"((c)[3])     \
                 : "r"((a)[0]), "r"((a)[1]), "r"((a)[2]), "r"((a)[3]),        \
                   "r"((b)[0]), "r"((b)[1]))

// 64-byte rows, 16B chunks, chunk ^= (row>>1)&3 -> ldmatrix conflict-free
__device__ __forceinline__ uint32_t tile_off(int row, int chunk) {
    return (uint32_t)(row * 64 + ((chunk ^ ((row >> 1) & 3)) * 16));
}

// ---------------------------------------------------------------------------
// dtype detection (int64 vs int32 index inputs)
// ---------------------------------------------------------------------------
__global__ void k_detect(const unsigned* __restrict__ ei,
                         const unsigned* __restrict__ bat, int E, int N) {
    __shared__ int s_ei, s_b;
    if (threadIdx.x == 0) { s_ei = 0; s_b = 0; }
    __syncthreads();
    int ne = (E < 1024) ? E : 1024;
    for (int i = threadIdx.x; i < ne; i += blockDim.x)
        if (ei[2 * i + 1]) atomicOr(&s_ei, 1);
    int base = N / 2 - 256; if (base < 0) base = 0;
    int nb2 = (N / 2 > 256) ? 256 : N / 2;
    for (int j = threadIdx.x; j < nb2; j += blockDim.x)
        if (bat[2 * (base + j) + 1]) atomicOr(&s_b, 1);
    __syncthreads();
    if (threadIdx.x == 0) { g_ei64 = s_ei ? 0 : 1; g_b64 = s_b ? 0 : 1; }
}

__device__ __forceinline__ int load_idx(const void* p, int i, int is64) {
    return is64 ? (int)((const long long*)p)[i] : ((const int*)p)[i];
}

// ---------------------------------------------------------------------------
// CSR-by-dst preprocessing
// ---------------------------------------------------------------------------
__global__ void k_hist(const void* __restrict__ ei, int E) {
    int e = blockIdx.x * blockDim.x + threadIdx.x;
    if (e >= E) return;
    atomicAdd(&g_deg[load_idx(ei, E + e, g_ei64)], 1);
}

__global__ void k_scan(const int* __restrict__ in, int* __restrict__ out,
                       int* __restrict__ bsum, int n) {
    __shared__ int s[1024];
    int gid = blockIdx.x * 1024 + threadIdx.x;
    int v = (gid < n) ? in[gid] : 0;
    s[threadIdx.x] = v;
    __syncthreads();
    #pragma unroll
    for (int d = 1; d < 1024; d <<= 1) {
        int t = (threadIdx.x >= d) ? s[threadIdx.x - d] : 0;
        __syncthreads();
        s[threadIdx.x] += t;
        __syncthreads();
    }
    if (gid < n) out[gid] = s[threadIdx.x] - v;
    if (bsum != nullptr && threadIdx.x == 1023) bsum[blockIdx.x] = s[1023];
}

// writes both g_off and g_cur (scatter cursor copy fused in)
__global__ void k_scanadd(int* __restrict__ off, int* __restrict__ cur,
                          const int* __restrict__ bs2, int n, int E) {
    int gid = blockIdx.x * 1024 + threadIdx.x;
    if (gid < n) {
        int v = off[gid] + bs2[blockIdx.x];
        off[gid] = v;
        cur[gid] = v;
    }
    if (gid == 0) off[n] = E;
}

__global__ void k_scatter(const void* __restrict__ ei, int E) {
    int e = blockIdx.x * blockDim.x + threadIdx.x;
    if (e >= E) return;
    int is64 = g_ei64;
    int s = load_idx(ei, e, is64);
    int d = load_idx(ei, E + e, is64);
    int p = atomicAdd(&g_cur[d], 1);
    g_src[p] = s;
    g_wt[p] = rsqrtf((float)(g_deg[s] + 1));
}

// ---------------------------------------------------------------------------
// fp16 conversion of x, zero-padded to Mpad rows
// ---------------------------------------------------------------------------
__global__ void k_cvtX(const float* __restrict__ X, __half* __restrict__ Xo,
                       int M, int Mpad, int K) {
    size_t i = ((size_t)blockIdx.x * blockDim.x + threadIdx.x) * 4;
    if (i >= (size_t)Mpad * K) return;
    int row = (int)(i / K);
    float4 v = make_float4(0.f, 0.f, 0.f, 0.f);
    if (row < M) v = *(const float4*)(X + i);
    ((__half2*)(Xo + i))[0] = __floats2half2_rn(v.x, v.y);
    ((__half2*)(Xo + i))[1] = __floats2half2_rn(v.z, v.w);
}

// All three weights, transposed to [N x K] fp16, in one launch.
__global__ void k_cvtW(const float* __restrict__ W1, const float* __restrict__ W2,
                       const float* __restrict__ W3) {
    int t = blockIdx.x * blockDim.x + threadIdx.x;
    if (t < 131072) {                       // B1: N=256, K=512
        int n = t >> 9, k = t & 511;
        g_B1[t] = __float2half_rn(W1[(size_t)k * 256 + n]);
    } else if (t < 131072 + 32768) {        // B2: N=128, K=256
        int u = t - 131072;
        int n = u >> 8, k = u & 255;
        g_B2[u] = __float2half_rn(W2[(size_t)k * 128 + n]);
    } else if (t < 131072 + 32768 + 8192) { // B3: N=64, K=128
        int u = t - 163840;
        int n = u >> 7, k = u & 127;
        g_B3[u] = __float2half_rn(W3[(size_t)k * 64 + n]);
    }
}

// ---------------------------------------------------------------------------
// HMMA GEMM: C[M,N] = A[M,K] @ B[N,K]^T, fp16 in, fp32 accum, fp16 out.
// Tile 128 x BN x 32, 256 threads (8 warps = 4m x 2n), warp tile 32 x (BN/2).
// ---------------------------------------------------------------------------
template<int BN>
__global__ void __launch_bounds__(256, 1) k_gemm_mma(
    const __half* __restrict__ A, const __half* __restrict__ B,
    __half* __restrict__ C, int M, int N, int K)
{
    constexpr int SS = 8192 + BN * 64;
    constexpr int NT = BN / 16;
    constexpr int WN = BN / 2;
    extern __shared__ char smem[];
    uint32_t sb = smem_u32(smem);
    int tid = threadIdx.x, lane = tid & 31, wid = tid >> 5;
    int bm = blockIdx.x * 128, bn = blockIdx.y * BN;
    int warp_m = wid & 3, warp_n = wid >> 2;

    float acc[2][NT][4] = {};
    const int KC = K >> 5;

    auto load_stage = [&](int it, int s) {
        int k0 = it << 5;
        uint32_t base = sb + s * SS;
        #pragma unroll
        for (int u = 0; u < 2; u++) {
            int c = tid * 2 + u;
            int row = c >> 2, ch = c & 3;
            uint32_t off = tile_off(row, ch);
            cpa16(base + off, A + (size_t)(bm + row) * K + k0 + ch * 8);
        }
        #pragma unroll
        for (int u = 0; u < BN / 64; u++) {
            int c = tid + u * 256;
            int row = c >> 2, ch = c & 3;
            uint32_t off = tile_off(row, ch);
            cpa16(base + 8192 + off, B + (size_t)(bn + row) * K + k0 + ch * 8);
        }
        asm volatile("cp.async.commit_group;");
    };

    int a_row = warp_m * 32 + (lane & 15);
    int a_chi = lane >> 4;
    int blk = lane >> 3;
    int b_rl = ((blk >> 1) * 8) + (lane & 7);
    int b_chi = blk & 1;

    load_stage(0, 0);
    for (int it = 0; it < KC; it++) {
        int s = it & 1;
        if (it + 1 < KC) {
            load_stage(it + 1, s ^ 1);
            asm volatile("cp.async.wait_group 1;");
        } else {
            asm volatile("cp.async.wait_group 0;");
        }
        __syncthreads();
        uint32_t base = sb + s * SS;
        #pragma unroll
        for (int kk = 0; kk < 2; kk++) {
            uint32_t af[2][4];
            int ach = kk * 2 + a_chi;
            #pragma unroll
            for (int mt = 0; mt < 2; mt++) {
                uint32_t off = tile_off(a_row + mt * 16, ach);
                LDM4(af[mt], base + off);
            }
            #pragma unroll
            for (int h = 0; h < NT / 4; h++) {
                uint32_t bf[4][2];
                #pragma unroll
                for (int nt2 = 0; nt2 < 2; nt2++) {
                    uint32_t r4[4];
                    int brow = warp_n * WN + h * 32 + nt2 * 16 + b_rl;
                    uint32_t off = tile_off(brow, kk * 2 + b_chi);
                    LDM4(r4, base + 8192 + off);
                    bf[nt2 * 2][0] = r4[0]; bf[nt2 * 2][1] = r4[1];
                    bf[nt2 * 2 + 1][0] = r4[2]; bf[nt2 * 2 + 1][1] = r4[3];
                }
                #pragma unroll
                for (int mt = 0; mt < 2; mt++)
                    #pragma unroll
                    for (int j = 0; j < 4; j++)
                        MMAF16(acc[mt][h * 4 + j], af[mt], bf[j]);
            }
        }
        __syncthreads();
    }

    #pragma unroll
    for (int mt = 0; mt < 2; mt++)
        #pragma unroll
        for (int nt = 0; nt < NT; nt++) {
            int row0 = bm + warp_m * 32 + mt * 16 + (lane >> 2);
            int col = bn + warp_n * WN + nt * 8 + (lane & 3) * 2;
            if (row0 < M)
                *(__half2*)(C + (size_t)row0 * N + col) =
                    __floats2half2_rn(acc[mt][nt][0], acc[mt][nt][1]);
            if (row0 + 8 < M)
                *(__half2*)(C + (size_t)(row0 + 8) * N + col) =
                    __floats2half2_rn(acc[mt][nt][2], acc[mt][nt][3]);
        }
}

// ---------------------------------------------------------------------------
// Aggregation over fp16 H: Out[v] = dinv[v]*(dinv[v]*H[v] + sum wt*H[src]) + b
// Each thread covers 8 features (one uint4 = 8 halves); fp32 accumulate;
// edge loop unrolled x4 for MLP.
// ---------------------------------------------------------------------------
__global__ void k_agg(const __half* __restrict__ Hin, float* __restrict__ OutF,
                      __half* __restrict__ OutH,
                      const float* __restrict__ bias, int N, int Mpad, int relu) {
    int v = blockIdx.x * blockDim.y + threadIdx.y;
    if (v >= Mpad) return;
    int F8 = blockDim.x;
    int x = threadIdx.x;
    int F = F8 * 8;
    if (v >= N) {
        if (OutH)
            ((uint4*)(OutH + (size_t)v * F))[x] = make_uint4(0, 0, 0, 0);
        return;
    }
    const uint4* H4 = (const uint4*)Hin;
    float dv = rsqrtf((float)(g_deg[v] + 1));
    float acc[8];
    {
        uint4 hv = H4[(size_t)v * F8 + x];
        const __half2* p = (const __half2*)&hv;
        #pragma unroll
        for (int q = 0; q < 4; q++) {
            float2 f = __half22float2(p[q]);
            acc[q * 2] = dv * f.x;
            acc[q * 2 + 1] = dv * f.y;
        }
    }
    int e = g_off[v], end = g_off[v + 1];
    for (; e + 3 < end; e += 4) {
        int s0 = __ldg(&g_src[e]);
        int s1 = __ldg(&g_src[e + 1]);
        int s2 = __ldg(&g_src[e + 2]);
        int s3 = __ldg(&g_src[e + 3]);
        float w0 = __ldg(&g_wt[e]);
        float w1 = __ldg(&g_wt[e + 1]);
        float w2 = __ldg(&g_wt[e + 2]);
        float w3 = __ldg(&g_wt[e + 3]);
        uint4 h0 = H4[(size_t)s0 * F8 + x];
        uint4 h1 = H4[(size_t)s1 * F8 + x];
        uint4 h2 = H4[(size_t)s2 * F8 + x];
        uint4 h3 = H4[(size_t)s3 * F8 + x];
        const __half2* p0 = (const __half2*)&h0;
        const __half2* p1 = (const __half2*)&h1;
        const __half2* p2 = (const __half2*)&h2;
        const __half2* p3 = (const __half2*)&h3;
        #pragma unroll
        for (int q = 0; q < 4; q++) {
            float2 f0 = __half22float2(p0[q]);
            float2 f1 = __half22float2(p1[q]);
            float2 f2 = __half22float2(p2[q]);
            float2 f3 = __half22float2(p3[q]);
            acc[q * 2]     += w0 * f0.x + w1 * f1.x + w2 * f2.x + w3 * f3.x;
            acc[q * 2 + 1] += w0 * f0.y + w1 * f1.y + w2 * f2.y + w3 * f3.y;
        }
    }
    for (; e < end; e++) {
        int s0 = __ldg(&g_src[e]);
        float w0 = __ldg(&g_wt[e]);
        uint4 h0 = H4[(size_t)s0 * F8 + x];
        const __half2* p0 = (const __half2*)&h0;
        #pragma unroll
        for (int q = 0; q < 4; q++) {
            float2 f0 = __half22float2(p0[q]);
            acc[q * 2]     += w0 * f0.x;
            acc[q * 2 + 1] += w0 * f0.y;
        }
    }
    float o[8];
    {
        float4 b0 = ((const float4*)bias)[x * 2];
        float4 b1 = ((const float4*)bias)[x * 2 + 1];
        o[0] = dv * acc[0] + b0.x; o[1] = dv * acc[1] + b0.y;
        o[2] = dv * acc[2] + b0.z; o[3] = dv * acc[3] + b0.w;
        o[4] = dv * acc[4] + b1.x; o[5] = dv * acc[5] + b1.y;
        o[6] = dv * acc[6] + b1.z; o[7] = dv * acc[7] + b1.w;
    }
    if (relu) {
        #pragma unroll
        for (int q = 0; q < 8; q++) o[q] = fmaxf(o[q], 0.f);
    }
    if (OutF) {
        float4* d = (float4*)(OutF + (size_t)v * F + x * 8);
        d[0] = make_float4(o[0], o[1], o[2], o[3]);
        d[1] = make_float4(o[4], o[5], o[6], o[7]);
    }
    if (OutH) {
        __half2 hh[4];
        #pragma unroll
        for (int q = 0; q < 4; q++)
            hh[q] = __floats2half2_rn(o[q * 2], o[q * 2 + 1]);
        ((uint4*)(OutH + (size_t)v * F))[x] = *(uint4*)hh;
    }
}

// ---------------------------------------------------------------------------
// Fused mean-pool + head: one block per graph (batch sorted), computes the
// pooled 64-vector AND this graph's two outputs.
// ---------------------------------------------------------------------------
__global__ void k_poolfinal(const float* __restrict__ Afin,
                            const void* __restrict__ bat,
                            const float* __restrict__ Wl,
                            const float* __restrict__ bl,
                            float* __restrict__ out, int N) {
    int g = blockIdx.x;
    int t = threadIdx.x;
    int is64 = g_b64;
    int lo = 0, hi = N;
    while (lo < hi) { int m = (lo + hi) >> 1; if (load_idx(bat, m, is64) < g) lo = m + 1; else hi = m; }
    int lo2 = lo, hi2 = N;
    while (lo2 < hi2) { int m = (lo2 + hi2) >> 1; if (load_idx(bat, m, is64) < g + 1) lo2 = m + 1; else hi2 = m; }
    int f = t & 63, seg = t >> 6;
    float acc = 0.f;
    for (int v = lo + seg; v < lo2; v += 4)
        acc += Afin[(size_t)v * 64 + f];
    __shared__ float sm[256];
    __shared__ float pooled[64];
    sm[t] = acc;
    __syncthreads();
    if (t < 64)
        pooled[t] = sm[t] + sm[t + 64] + sm[t + 128] + sm[t + 192];
    __syncthreads();
    if (t < 2) {
        float cnt = fmaxf((float)(lo2 - lo), 1.0f);
        float s = 0.f;
        #pragma unroll
        for (int ff = 0; ff < 64; ff++) s += pooled[ff] * Wl[ff * 2 + t];
        out[g * 2 + t] = s / cnt + bl[t];
    }
}

// ---------------------------------------------------------------------------
// Orchestration
// ---------------------------------------------------------------------------
extern "C" void kernel_launch(void* const* d_in, const int* in_sizes, int n_in,
                              void* d_out, int out_size) {
    const float* x   = (const float*)d_in[0];
    const void*  ei  = d_in[1];
    const void*  bat = d_in[2];
    const float* W1 = (const float*)d_in[3];
    const float* b1 = (const float*)d_in[4];
    const float* W2 = (const float*)d_in[5];
    const float* b2 = (const float*)d_in[6];
    const float* W3 = (const float*)d_in[7];
    const float* b3 = (const float*)d_in[8];
    const float* Wl = (const float*)d_in[9];
    const float* bl = (const float*)d_in[10];
    float* out = (float*)d_out;

    int N = in_sizes[0] / 512;
    int E = in_sizes[1] / 2;
    int G = out_size / 2;
    int mt = (N + 127) / 128;
    int Mpad = mt * 128;

    static int inited = 0;
    static cudaStream_t s2;
    static cudaEvent_t ev1, ev_w, ev_csr;
    if (!inited) {
        cudaFuncSetAttribute(k_gemm_mma<128>, cudaFuncAttributeMaxDynamicSharedMemorySize, 32768);
        cudaFuncSetAttribute(k_gemm_mma<64>, cudaFuncAttributeMaxDynamicSharedMemorySize, 24576);
        cudaStreamCreateWithFlags(&s2, cudaStreamNonBlocking);
        cudaEventCreateWithFlags(&ev1, cudaEventDisableTiming);
        cudaEventCreateWithFlags(&ev_w, cudaEventDisableTiming);
        cudaEventCreateWithFlags(&ev_csr, cudaEventDisableTiming);
        inited = 1;
    }

    void *p_deg, *p_off, *p_cur, *p_bs, *p_bs2, *p_H, *p_A, *p_X;
    void *p_B1, *p_B2, *p_B3;
    cudaGetSymbolAddress(&p_deg, g_deg);
    cudaGetSymbolAddress(&p_off, g_off);
    cudaGetSymbolAddress(&p_cur, g_cur);
    cudaGetSymbolAddress(&p_bs, g_bs);
    cudaGetSymbolAddress(&p_bs2, g_bs2);
    cudaGetSymbolAddress(&p_H, g_H);
    cudaGetSymbolAddress(&p_A, g_A);
    cudaGetSymbolAddress(&p_X, g_X);
    cudaGetSymbolAddress(&p_B1, g_B1);
    cudaGetSymbolAddress(&p_B2, g_B2);
    cudaGetSymbolAddress(&p_B3, g_B3);

    const __half* Xp = (const __half*)p_X;

    // ---- fork: weight convert + CSR preprocessing on side stream --------
    cudaEventRecord(ev1, 0);
    cudaStreamWaitEvent(s2, ev1, 0);
    k_cvtW<<<(172032 + 255) / 256, 256, 0, s2>>>(W1, W2, W3);
    cudaEventRecord(ev_w, s2);
    cudaMemsetAsync(p_deg, 0, N * sizeof(int), s2);
    k_detect<<<1, 256, 0, s2>>>((const unsigned*)ei, (const unsigned*)bat, E, N);
    k_hist<<<(E + 255) / 256, 256, 0, s2>>>(ei, E);
    int nb = (N + 1023) / 1024;
    k_scan<<<nb, 1024, 0, s2>>>((const int*)p_deg, (int*)p_off, (int*)p_bs, N);
    k_scan<<<1, 1024, 0, s2>>>((const int*)p_bs, (int*)p_bs2, nullptr, nb);
    k_scanadd<<<nb, 1024, 0, s2>>>((int*)p_off, (int*)p_cur, (const int*)p_bs2, N, E);
    k_scatter<<<(E + 255) / 256, 256, 0, s2>>>(ei, E);
    cudaEventRecord(ev_csr, s2);

    // ---- main: layer-1 convert + GEMM -----------------------------------
    {
        size_t tot = (size_t)Mpad * 512 / 4;
        k_cvtX<<<(int)((tot + 255) / 256), 256>>>(x, (__half*)p_X, N, Mpad, 512);
        cudaStreamWaitEvent(0, ev_w, 0);
        k_gemm_mma<128><<<dim3(mt, 2), 256, 32768>>>(Xp, (const __half*)p_B1,
                                                     (__half*)p_H, N, 256, 512);
    }
    // ---- join: aggregation needs CSR ------------------------------------
    cudaStreamWaitEvent(0, ev_csr, 0);
    {
        int gb = (Mpad + 7) / 8;
        k_agg<<<gb, dim3(32, 8)>>>((const __half*)p_H, nullptr,
                                   (__half*)p_X, b1, N, Mpad, 1);
    }
    // ---- layer 2 --------------------------------------------------------
    {
        k_gemm_mma<128><<<dim3(mt, 1), 256, 32768>>>(Xp, (const __half*)p_B2,
                                                     (__half*)p_H, N, 128, 256);
        int gb = (Mpad + 15) / 16;
        k_agg<<<gb, dim3(16, 16)>>>((const __half*)p_H, nullptr,
                                    (__half*)p_X, b2, N, Mpad, 1);
    }
    // ---- layer 3 --------------------------------------------------------
    {
        k_gemm_mma<64><<<dim3(mt, 1), 256, 24576>>>(Xp, (const __half*)p_B3,
                                                    (__half*)p_H, N, 64, 128);
        int gb = (N + 31) / 32;
        k_agg<<<gb, dim3(8, 32)>>>((const __half*)p_H, (float*)p_A,
                                   nullptr, b3, N, N, 0);
    }

    // ---- fused pool + head ----------------------------------------------
    k_poolfinal<<<G, 256>>>((const float*)p_A, bat, Wl, bl, out, N);
}

// round 8
// speedup vs baseline: 3.9078x; 1.0484x over previous
#include <cuda_runtime.h>
#include <cuda_fp16.h>
#include <cstdint>
#include <cstddef>

// ---------------------------------------------------------------------------
// GCN_27874337751415 round 8: conversion fused into GEMM-1 A-loader,
// single-pass lookback scan, cvtW on 3rd stream, 8x unrolled gather.
// ---------------------------------------------------------------------------

#define MAXN 50176
#define MAXE 800000

__device__ int   g_deg[MAXN];
__device__ int   g_off[MAXN + 1];
__device__ int   g_cur[MAXN];
__device__ int   g_flag[64];
__device__ int   g_src[MAXE];
__device__ float g_wt[MAXE];
__device__ __align__(16) __half g_H[(size_t)MAXN * 256];   // GEMM out, fp16
__device__ __align__(16) float  g_A[(size_t)MAXN * 64];    // layer-3 agg out
__device__ __align__(16) __half g_X[(size_t)MAXN * 256];   // agg out = GEMM A
__device__ __align__(16) __half g_B1[512 * 256];
__device__ __align__(16) __half g_B2[256 * 128];
__device__ __align__(16) __half g_B3[128 * 64];
__device__ int   g_ei64;
__device__ int   g_b64;

// ---------------------------------------------------------------------------
// helpers
// ---------------------------------------------------------------------------
__device__ __forceinline__ uint32_t smem_u32(const void* p) {
    uint32_t a;
    asm("{ .reg .u64 t; cvta.to.shared.u64 t, %1; cvt.u32.u64 %0, t; }"
        : "=r"(a) : "l"(p));
    return a;
}
__device__ __forceinline__ void cpa16(uint32_t s, const void* g) {
    asm volatile("cp.async.cg.shared.global [%0], [%1], 16;" :: "r"(s), "l"(g));
}
#define LDM4(r, addr)                                                         \
    asm volatile("ldmatrix.sync.aligned.m8n8.x4.shared.b16 {%0,%1,%2,%3}, [%4];" \
                 : "=r"((r)[0]), "=r"((r)[1]), "=r"((r)[2]), "=r"((r)[3])     \
                 : "r"(addr))
#define MMAF16(c, a, b)                                                       \
    asm volatile("mma.sync.aligned.m16n8k16.row.col.f32.f16.f16.f32 "         \
                 "{%0,%1,%2,%3},{%4,%5,%6,%7},{%8,%9},{%0,%1,%2,%3};"         \
                 : "+f"((c)[0]), "+f"((c)[1]), "+f"((c)[2]), "+f"((c)[3])     \
                 : "r"((a)[0]), "r"((a)[1]), "r"((a)[2]), "r"((a)[3]),        \
                   "r"((b)[0]), "r"((b)[1]))

// 64-byte rows, 16B chunks, chunk ^= (row>>1)&3 -> ldmatrix conflict-free
__device__ __forceinline__ uint32_t tile_off(int row, int chunk) {
    return (uint32_t)(row * 64 + ((chunk ^ ((row >> 1) & 3)) * 16));
}

// ---------------------------------------------------------------------------
// dtype detection + zeroing of g_deg / g_flag (block 0 detects, all zero)
// ---------------------------------------------------------------------------
__global__ void k_detect(const unsigned* __restrict__ ei,
                         const unsigned* __restrict__ bat, int E, int N) {
    int gid = blockIdx.x * blockDim.x + threadIdx.x;
    for (int i = gid; i < MAXN; i += gridDim.x * blockDim.x) g_deg[i] = 0;
    if (gid < 64) g_flag[gid] = 0;
    if (blockIdx.x == 0) {
        __shared__ int s_ei, s_b;
        if (threadIdx.x == 0) { s_ei = 0; s_b = 0; }
        __syncthreads();
        int ne = (E < 1024) ? E : 1024;
        for (int i = threadIdx.x; i < ne; i += blockDim.x)
            if (ei[2 * i + 1]) atomicOr(&s_ei, 1);
        int base = N / 2 - 256; if (base < 0) base = 0;
        int nb2 = (N / 2 > 256) ? 256 : N / 2;
        for (int j = threadIdx.x; j < nb2; j += blockDim.x)
            if (bat[2 * (base + j) + 1]) atomicOr(&s_b, 1);
        __syncthreads();
        if (threadIdx.x == 0) { g_ei64 = s_ei ? 0 : 1; g_b64 = s_b ? 0 : 1; }
    }
}

__device__ __forceinline__ int load_idx(const void* p, int i, int is64) {
    return is64 ? (int)((const long long*)p)[i] : ((const int*)p)[i];
}

// ---------------------------------------------------------------------------
// CSR-by-dst preprocessing
// ---------------------------------------------------------------------------
__global__ void k_hist(const void* __restrict__ ei, int E) {
    int e = blockIdx.x * blockDim.x + threadIdx.x;
    if (e >= E) return;
    atomicAdd(&g_deg[load_idx(ei, E + e, g_ei64)], 1);
}

// Single-pass exclusive scan with decoupled lookback. 49 blocks, all resident
// in wave 1 (<=148 SMs); each block publishes (blocksum+1) into one atomic
// word BEFORE waiting, so no deadlock and no separate flag/value ordering.
__global__ void k_scan1(const int* __restrict__ in, int* __restrict__ off,
                        int* __restrict__ cur, int n, int E) {
    __shared__ int s[1024];
    __shared__ int s_pfx;
    int bid = blockIdx.x;
    int gid = bid * 1024 + threadIdx.x;
    int v = (gid < n) ? in[gid] : 0;
    s[threadIdx.x] = v;
    __syncthreads();
    #pragma unroll
    for (int d = 1; d < 1024; d <<= 1) {
        int t = (threadIdx.x >= d) ? s[threadIdx.x - d] : 0;
        __syncthreads();
        s[threadIdx.x] += t;
        __syncthreads();
    }
    if (threadIdx.x == 0) {
        atomicExch(&g_flag[bid], s[1023] + 1);
        int pfx = 0;
        for (int i = 0; i < bid; i++) {
            int f;
            while ((f = atomicAdd(&g_flag[i], 0)) == 0) {}
            pfx += f - 1;
        }
        s_pfx = pfx;
    }
    __syncthreads();
    if (gid < n) {
        int o = s_pfx + s[threadIdx.x] - v;
        off[gid] = o;
        cur[gid] = o;
    }
    if (bid == (int)gridDim.x - 1 && threadIdx.x == 1023) off[n] = E;
}

__global__ void k_scatter(const void* __restrict__ ei, int E) {
    int e = blockIdx.x * blockDim.x + threadIdx.x;
    if (e >= E) return;
    int is64 = g_ei64;
    int s = load_idx(ei, e, is64);
    int d = load_idx(ei, E + e, is64);
    int p = atomicAdd(&g_cur[d], 1);
    g_src[p] = s;
    g_wt[p] = rsqrtf((float)(g_deg[s] + 1));
}

// All three weights, transposed to [N x K] fp16, in one launch.
__global__ void k_cvtW(const float* __restrict__ W1, const float* __restrict__ W2,
                       const float* __restrict__ W3) {
    int t = blockIdx.x * blockDim.x + threadIdx.x;
    if (t < 131072) {                       // B1: N=256, K=512
        int n = t >> 9, k = t & 511;
        g_B1[t] = __float2half_rn(W1[(size_t)k * 256 + n]);
    } else if (t < 131072 + 32768) {        // B2: N=128, K=256
        int u = t - 131072;
        int n = u >> 8, k = u & 255;
        g_B2[u] = __float2half_rn(W2[(size_t)k * 128 + n]);
    } else if (t < 131072 + 32768 + 8192) { // B3: N=64, K=128
        int u = t - 163840;
        int n = u >> 7, k = u & 127;
        g_B3[u] = __float2half_rn(W3[(size_t)k * 64 + n]);
    }
}

// ---------------------------------------------------------------------------
// HMMA GEMM: C[M,N] = A[M,K] @ B[N,K]^T, fp32 accum, fp16 out.
// CVT=true: A is fp32 in gmem; loader LDGs, converts, STS (register-staged,
// double-buffered so the LDG latency hides under compute). Rows >= M read 0.
// CVT=false: A is fp16, cp.async path (rows up to Mpad are valid/zeroed).
// Tile 128 x BN x 32, 256 threads (8 warps = 4m x 2n).
// ---------------------------------------------------------------------------
template<int BN, bool CVT>
__global__ void __launch_bounds__(256, 1) k_gemm_mma(
    const void* __restrict__ Av, const __half* __restrict__ B,
    __half* __restrict__ C, int M, int N, int K)
{
    constexpr int SS = 8192 + BN * 64;
    constexpr int NT = BN / 16;
    constexpr int WN = BN / 2;
    extern __shared__ char smem[];
    uint32_t sb = smem_u32(smem);
    int tid = threadIdx.x, lane = tid & 31, wid = tid >> 5;
    int bm = blockIdx.x * 128, bn = blockIdx.y * BN;
    int warp_m = wid & 3, warp_n = wid >> 2;
    const __half* A = (const __half*)Av;
    const float* Af = (const float*)Av;

    float acc[2][NT][4] = {};
    const int KC = K >> 5;
    float4 a4[4];

    auto ldgA = [&](int it) {
        int k0 = it << 5;
        #pragma unroll
        for (int u = 0; u < 4; u++) {
            int c = u * 256 + tid;
            int row = c >> 3, ch8 = c & 7;
            int grow = bm + row;
            if (grow < M)
                a4[u] = *(const float4*)(Af + (size_t)grow * K + k0 + ch8 * 4);
            else
                a4[u] = make_float4(0.f, 0.f, 0.f, 0.f);
        }
    };
    auto stsA = [&](int s) {
        uint32_t base = sb + s * SS;
        #pragma unroll
        for (int u = 0; u < 4; u++) {
            int c = u * 256 + tid;
            int row = c >> 3, ch8 = c & 7;
            uint32_t off = tile_off(row, ch8 >> 1) + (ch8 & 1) * 8;
            __half2 h0 = __floats2half2_rn(a4[u].x, a4[u].y);
            __half2 h1 = __floats2half2_rn(a4[u].z, a4[u].w);
            asm volatile("st.shared.v2.b32 [%0], {%1,%2};"
                         :: "r"(base + off), "r"(*(uint32_t*)&h0), "r"(*(uint32_t*)&h1));
        }
    };
    auto ldA_async = [&](int it, int s) {
        int k0 = it << 5;
        uint32_t base = sb + s * SS;
        #pragma unroll
        for (int u = 0; u < 2; u++) {
            int c = tid * 2 + u;
            int row = c >> 2, ch = c & 3;
            cpa16(base + tile_off(row, ch), A + (size_t)(bm + row) * K + k0 + ch * 8);
        }
    };
    auto ldB = [&](int it, int s) {
        int k0 = it << 5;
        uint32_t base = sb + s * SS;
        #pragma unroll
        for (int u = 0; u < BN / 64; u++) {
            int c = tid + u * 256;
            int row = c >> 2, ch = c & 3;
            cpa16(base + 8192 + tile_off(row, ch), B + (size_t)(bn + row) * K + k0 + ch * 8);
        }
    };

    if constexpr (CVT) {
        ldgA(0);
        ldB(0, 0);
        asm volatile("cp.async.commit_group;");
        stsA(0);
    } else {
        ldA_async(0, 0);
        ldB(0, 0);
        asm volatile("cp.async.commit_group;");
    }

    int a_row = warp_m * 32 + (lane & 15);
    int a_chi = lane >> 4;
    int blk = lane >> 3;
    int b_rl = ((blk >> 1) * 8) + (lane & 7);
    int b_chi = blk & 1;

    for (int it = 0; it < KC; it++) {
        int s = it & 1;
        if (it + 1 < KC) {
            if constexpr (CVT) {
                ldgA(it + 1);
                ldB(it + 1, s ^ 1);
            } else {
                ldA_async(it + 1, s ^ 1);
                ldB(it + 1, s ^ 1);
            }
            asm volatile("cp.async.commit_group;");
            asm volatile("cp.async.wait_group 1;");
        } else {
            asm volatile("cp.async.wait_group 0;");
        }
        __syncthreads();
        uint32_t base = sb + s * SS;
        #pragma unroll
        for (int kk = 0; kk < 2; kk++) {
            uint32_t af[2][4];
            int ach = kk * 2 + a_chi;
            #pragma unroll
            for (int mt = 0; mt < 2; mt++) {
                uint32_t off = tile_off(a_row + mt * 16, ach);
                LDM4(af[mt], base + off);
            }
            #pragma unroll
            for (int h = 0; h < NT / 4; h++) {
                uint32_t bf[4][2];
                #pragma unroll
                for (int nt2 = 0; nt2 < 2; nt2++) {
                    uint32_t r4[4];
                    int brow = warp_n * WN + h * 32 + nt2 * 16 + b_rl;
                    uint32_t off = tile_off(brow, kk * 2 + b_chi);
                    LDM4(r4, base + 8192 + off);
                    bf[nt2 * 2][0] = r4[0]; bf[nt2 * 2][1] = r4[1];
                    bf[nt2 * 2 + 1][0] = r4[2]; bf[nt2 * 2 + 1][1] = r4[3];
                }
                #pragma unroll
                for (int mt = 0; mt < 2; mt++)
                    #pragma unroll
                    for (int j = 0; j < 4; j++)
                        MMAF16(acc[mt][h * 4 + j], af[mt], bf[j]);
            }
        }
        __syncthreads();
        if constexpr (CVT) {
            if (it + 1 < KC) stsA(s ^ 1);
        }
    }

    #pragma unroll
    for (int mt = 0; mt < 2; mt++)
        #pragma unroll
        for (int nt = 0; nt < NT; nt++) {
            int row0 = bm + warp_m * 32 + mt * 16 + (lane >> 2);
            int col = bn + warp_n * WN + nt * 8 + (lane & 3) * 2;
            if (row0 < M)
                *(__half2*)(C + (size_t)row0 * N + col) =
                    __floats2half2_rn(acc[mt][nt][0], acc[mt][nt][1]);
            if (row0 + 8 < M)
                *(__half2*)(C + (size_t)(row0 + 8) * N + col) =
                    __floats2half2_rn(acc[mt][nt][2], acc[mt][nt][3]);
        }
}

// ---------------------------------------------------------------------------
// Aggregation over fp16 H: Out[v] = dinv[v]*(dinv[v]*H[v] + sum wt*H[src]) + b
// Each thread covers 8 features (one uint4); fp32 accumulate; 8x unroll.
// ---------------------------------------------------------------------------
__global__ void k_agg(const __half* __restrict__ Hin, float* __restrict__ OutF,
                      __half* __restrict__ OutH,
                      const float* __restrict__ bias, int N, int Mpad, int relu) {
    int v = blockIdx.x * blockDim.y + threadIdx.y;
    if (v >= Mpad) return;
    int F8 = blockDim.x;
    int x = threadIdx.x;
    int F = F8 * 8;
    if (v >= N) {
        if (OutH)
            ((uint4*)(OutH + (size_t)v * F))[x] = make_uint4(0, 0, 0, 0);
        return;
    }
    const uint4* H4 = (const uint4*)Hin;
    float dv = rsqrtf((float)(g_deg[v] + 1));
    float acc[8];
    {
        uint4 hv = H4[(size_t)v * F8 + x];
        const __half2* p = (const __half2*)&hv;
        #pragma unroll
        for (int q = 0; q < 4; q++) {
            float2 f = __half22float2(p[q]);
            acc[q * 2] = dv * f.x;
            acc[q * 2 + 1] = dv * f.y;
        }
    }
    int e = g_off[v], end = g_off[v + 1];
    for (; e + 7 < end; e += 8) {
        int sv[8]; float wv[8]; uint4 hv[8];
        #pragma unroll
        for (int j = 0; j < 8; j++) {
            sv[j] = __ldg(&g_src[e + j]);
            wv[j] = __ldg(&g_wt[e + j]);
        }
        #pragma unroll
        for (int j = 0; j < 8; j++)
            hv[j] = H4[(size_t)sv[j] * F8 + x];
        #pragma unroll
        for (int j = 0; j < 8; j++) {
            const __half2* p = (const __half2*)&hv[j];
            #pragma unroll
            for (int q = 0; q < 4; q++) {
                float2 f = __half22float2(p[q]);
                acc[q * 2]     += wv[j] * f.x;
                acc[q * 2 + 1] += wv[j] * f.y;
            }
        }
    }
    for (; e + 3 < end; e += 4) {
        int sv[4]; float wv[4]; uint4 hv[4];
        #pragma unroll
        for (int j = 0; j < 4; j++) {
            sv[j] = __ldg(&g_src[e + j]);
            wv[j] = __ldg(&g_wt[e + j]);
        }
        #pragma unroll
        for (int j = 0; j < 4; j++)
            hv[j] = H4[(size_t)sv[j] * F8 + x];
        #pragma unroll
        for (int j = 0; j < 4; j++) {
            const __half2* p = (const __half2*)&hv[j];
            #pragma unroll
            for (int q = 0; q < 4; q++) {
                float2 f = __half22float2(p[q]);
                acc[q * 2]     += wv[j] * f.x;
                acc[q * 2 + 1] += wv[j] * f.y;
            }
        }
    }
    for (; e < end; e++) {
        int s0 = __ldg(&g_src[e]);
        float w0 = __ldg(&g_wt[e]);
        uint4 h0 = H4[(size_t)s0 * F8 + x];
        const __half2* p0 = (const __half2*)&h0;
        #pragma unroll
        for (int q = 0; q < 4; q++) {
            float2 f0 = __half22float2(p0[q]);
            acc[q * 2]     += w0 * f0.x;
            acc[q * 2 + 1] += w0 * f0.y;
        }
    }
    float o[8];
    {
        float4 b0 = ((const float4*)bias)[x * 2];
        float4 b1 = ((const float4*)bias)[x * 2 + 1];
        o[0] = dv * acc[0] + b0.x; o[1] = dv * acc[1] + b0.y;
        o[2] = dv * acc[2] + b0.z; o[3] = dv * acc[3] + b0.w;
        o[4] = dv * acc[4] + b1.x; o[5] = dv * acc[5] + b1.y;
        o[6] = dv * acc[6] + b1.z; o[7] = dv * acc[7] + b1.w;
    }
    if (relu) {
        #pragma unroll
        for (int q = 0; q < 8; q++) o[q] = fmaxf(o[q], 0.f);
    }
    if (OutF) {
        float4* d = (float4*)(OutF + (size_t)v * F + x * 8);
        d[0] = make_float4(o[0], o[1], o[2], o[3]);
        d[1] = make_float4(o[4], o[5], o[6], o[7]);
    }
    if (OutH) {
        __half2 hh[4];
        #pragma unroll
        for (int q = 0; q < 4; q++)
            hh[q] = __floats2half2_rn(o[q * 2], o[q * 2 + 1]);
        ((uint4*)(OutH + (size_t)v * F))[x] = *(uint4*)hh;
    }
}

// ---------------------------------------------------------------------------
// Fused mean-pool + head: one block per graph (batch sorted).
// ---------------------------------------------------------------------------
__global__ void k_poolfinal(const float* __restrict__ Afin,
                            const void* __restrict__ bat,
                            const float* __restrict__ Wl,
                            const float* __restrict__ bl,
                            float* __restrict__ out, int N) {
    int g = blockIdx.x;
    int t = threadIdx.x;
    int is64 = g_b64;
    int lo = 0, hi = N;
    while (lo < hi) { int m = (lo + hi) >> 1; if (load_idx(bat, m, is64) < g) lo = m + 1; else hi = m; }
    int lo2 = lo, hi2 = N;
    while (lo2 < hi2) { int m = (lo2 + hi2) >> 1; if (load_idx(bat, m, is64) < g + 1) lo2 = m + 1; else hi2 = m; }
    int f = t & 63, seg = t >> 6;
    float acc = 0.f;
    for (int v = lo + seg; v < lo2; v += 4)
        acc += Afin[(size_t)v * 64 + f];
    __shared__ float sm[256];
    __shared__ float pooled[64];
    sm[t] = acc;
    __syncthreads();
    if (t < 64)
        pooled[t] = sm[t] + sm[t + 64] + sm[t + 128] + sm[t + 192];
    __syncthreads();
    if (t < 2) {
        float cnt = fmaxf((float)(lo2 - lo), 1.0f);
        float s = 0.f;
        #pragma unroll
        for (int ff = 0; ff < 64; ff++) s += pooled[ff] * Wl[ff * 2 + t];
        out[g * 2 + t] = s / cnt + bl[t];
    }
}

// ---------------------------------------------------------------------------
// Orchestration
// ---------------------------------------------------------------------------
extern "C" void kernel_launch(void* const* d_in, const int* in_sizes, int n_in,
                              void* d_out, int out_size) {
    const float* x   = (const float*)d_in[0];
    const void*  ei  = d_in[1];
    const void*  bat = d_in[2];
    const float* W1 = (const float*)d_in[3];
    const float* b1 = (const float*)d_in[4];
    const float* W2 = (const float*)d_in[5];
    const float* b2 = (const float*)d_in[6];
    const float* W3 = (const float*)d_in[7];
    const float* b3 = (const float*)d_in[8];
    const float* Wl = (const float*)d_in[9];
    const float* bl = (const float*)d_in[10];
    float* out = (float*)d_out;

    int N = in_sizes[0] / 512;
    int E = in_sizes[1] / 2;
    int G = out_size / 2;
    int mt = (N + 127) / 128;
    int Mpad = mt * 128;

    static int inited = 0;
    static cudaStream_t s2, s3;
    static cudaEvent_t ev1, ev_w, ev_csr;
    if (!inited) {
        cudaFuncSetAttribute((const void*)k_gemm_mma<128, true>,
                             cudaFuncAttributeMaxDynamicSharedMemorySize, 32768);
        cudaFuncSetAttribute((const void*)k_gemm_mma<128, false>,
                             cudaFuncAttributeMaxDynamicSharedMemorySize, 32768);
        cudaFuncSetAttribute((const void*)k_gemm_mma<64, false>,
                             cudaFuncAttributeMaxDynamicSharedMemorySize, 24576);
        cudaStreamCreateWithFlags(&s2, cudaStreamNonBlocking);
        cudaStreamCreateWithFlags(&s3, cudaStreamNonBlocking);
        cudaEventCreateWithFlags(&ev1, cudaEventDisableTiming);
        cudaEventCreateWithFlags(&ev_w, cudaEventDisableTiming);
        cudaEventCreateWithFlags(&ev_csr, cudaEventDisableTiming);
        inited = 1;
    }

    void *p_deg, *p_off, *p_cur, *p_H, *p_A, *p_X, *p_B1, *p_B2, *p_B3;
    cudaGetSymbolAddress(&p_deg, g_deg);
    cudaGetSymbolAddress(&p_off, g_off);
    cudaGetSymbolAddress(&p_cur, g_cur);
    cudaGetSymbolAddress(&p_H, g_H);
    cudaGetSymbolAddress(&p_A, g_A);
    cudaGetSymbolAddress(&p_X, g_X);
    cudaGetSymbolAddress(&p_B1, g_B1);
    cudaGetSymbolAddress(&p_B2, g_B2);
    cudaGetSymbolAddress(&p_B3, g_B3);

    // ---- fork -----------------------------------------------------------
    cudaEventRecord(ev1, 0);
    cudaStreamWaitEvent(s2, ev1, 0);
    cudaStreamWaitEvent(s3, ev1, 0);
    // s3: weight convert only (gates gemm1)
    k_cvtW<<<(172032 + 255) / 256, 256, 0, s3>>>(W1, W2, W3);
    cudaEventRecord(ev_w, s3);
    // s2: CSR build (gates agg1)
    k_detect<<<64, 256, 0, s2>>>((const unsigned*)ei, (const unsigned*)bat, E, N);
    k_hist<<<(E + 255) / 256, 256, 0, s2>>>(ei, E);
    int nb = (N + 1023) / 1024;
    k_scan1<<<nb, 1024, 0, s2>>>((const int*)p_deg, (int*)p_off, (int*)p_cur, N, E);
    k_scatter<<<(E + 255) / 256, 256, 0, s2>>>(ei, E);
    cudaEventRecord(ev_csr, s2);

    // ---- main: layer-1 GEMM with fused fp32->fp16 conversion ------------
    cudaStreamWaitEvent(0, ev_w, 0);
    k_gemm_mma<128, true><<<dim3(mt, 2), 256, 32768>>>(
        x, (const __half*)p_B1, (__half*)p_H, N, 256, 512);

    // ---- join: aggregation needs CSR ------------------------------------
    cudaStreamWaitEvent(0, ev_csr, 0);
    {
        int gb = (Mpad + 7) / 8;
        k_agg<<<gb, dim3(32, 8)>>>((const __half*)p_H, nullptr,
                                   (__half*)p_X, b1, N, Mpad, 1);
    }
    // ---- layer 2 --------------------------------------------------------
    {
        k_gemm_mma<128, false><<<dim3(mt, 1), 256, 32768>>>(
            p_X, (const __half*)p_B2, (__half*)p_H, N, 128, 256);
        int gb = (Mpad + 15) / 16;
        k_agg<<<gb, dim3(16, 16)>>>((const __half*)p_H, nullptr,
                                    (__half*)p_X, b2, N, Mpad, 1);
    }
    // ---- layer 3 --------------------------------------------------------
    {
        k_gemm_mma<64, false><<<dim3(mt, 1), 256, 24576>>>(
            p_X, (const __half*)p_B3, (__half*)p_H, N, 64, 128);
        int gb = (N + 31) / 32;
        k_agg<<<gb, dim3(8, 32)>>>((const __half*)p_H, (float*)p_A,
                                   nullptr, b3, N, N, 0);
    }

    // ---- fused pool + head ----------------------------------------------
    k_poolfinal<<<G, 256>>>((const float*)p_A, bat, Wl, bl, out, N);
}

// round 9
// speedup vs baseline: 4.1093x; 1.0516x over previous
#include <cuda_runtime.h>
#include <cuda_fp16.h>
#include <cstdint>
#include <cstddef>

// ---------------------------------------------------------------------------
// GCN_27874337751415 round 9: warp-parallel lookback scan, packed (src,wt)
// edge records, n-major GEMM grid for L2 reuse of A.
// ---------------------------------------------------------------------------

#define MAXN 50176
#define MAXE 800000

__device__ int   g_deg[MAXN];
__device__ int   g_off[MAXN + 1];
__device__ int   g_cur[MAXN];
__device__ int   g_flag[64];
__device__ int2  g_sw[MAXE];                                // {src, f32 wt bits}
__device__ __align__(16) __half g_H[(size_t)MAXN * 256];   // GEMM out, fp16
__device__ __align__(16) float  g_A[(size_t)MAXN * 64];    // layer-3 agg out
__device__ __align__(16) __half g_X[(size_t)MAXN * 256];   // agg out = GEMM A
__device__ __align__(16) __half g_B1[512 * 256];
__device__ __align__(16) __half g_B2[256 * 128];
__device__ __align__(16) __half g_B3[128 * 64];
__device__ int   g_ei64;
__device__ int   g_b64;

// ---------------------------------------------------------------------------
// helpers
// ---------------------------------------------------------------------------
__device__ __forceinline__ uint32_t smem_u32(const void* p) {
    uint32_t a;
    asm("{ .reg .u64 t; cvta.to.shared.u64 t, %1; cvt.u32.u64 %0, t; }"
        : "=r"(a) : "l"(p));
    return a;
}
__device__ __forceinline__ void cpa16(uint32_t s, const void* g) {
    asm volatile("cp.async.cg.shared.global [%0], [%1], 16;" :: "r"(s), "l"(g));
}
#define LDM4(r, addr)                                                         \
    asm volatile("ldmatrix.sync.aligned.m8n8.x4.shared.b16 {%0,%1,%2,%3}, [%4];" \
                 : "=r"((r)[0]), "=r"((r)[1]), "=r"((r)[2]), "=r"((r)[3])     \
                 : "r"(addr))
#define MMAF16(c, a, b)                                                       \
    asm volatile("mma.sync.aligned.m16n8k16.row.col.f32.f16.f16.f32 "         \
                 "{%0,%1,%2,%3},{%4,%5,%6,%7},{%8,%9},{%0,%1,%2,%3};"         \
                 : "+f"((c)[0]), "+f"((c)[1]), "+f"((c)[2]), "+f"((c)[3])     \
                 : "r"((a)[0]), "r"((a)[1]), "r"((a)[2]), "r"((a)[3]),        \
                   "r"((b)[0]), "r"((b)[1]))

// 64-byte rows, 16B chunks, chunk ^= (row>>1)&3 -> ldmatrix conflict-free
__device__ __forceinline__ uint32_t tile_off(int row, int chunk) {
    return (uint32_t)(row * 64 + ((chunk ^ ((row >> 1) & 3)) * 16));
}

// ---------------------------------------------------------------------------
// dtype detection + zeroing of g_deg / g_flag (block 0 detects, all zero)
// ---------------------------------------------------------------------------
__global__ void k_detect(const unsigned* __restrict__ ei,
                         const unsigned* __restrict__ bat, int E, int N) {
    int gid = blockIdx.x * blockDim.x + threadIdx.x;
    for (int i = gid; i < MAXN; i += gridDim.x * blockDim.x) g_deg[i] = 0;
    if (gid < 64) g_flag[gid] = 0;
    if (blockIdx.x == 0) {
        __shared__ int s_ei, s_b;
        if (threadIdx.x == 0) { s_ei = 0; s_b = 0; }
        __syncthreads();
        int ne = (E < 1024) ? E : 1024;
        for (int i = threadIdx.x; i < ne; i += blockDim.x)
            if (ei[2 * i + 1]) atomicOr(&s_ei, 1);
        int base = N / 2 - 256; if (base < 0) base = 0;
        int nb2 = (N / 2 > 256) ? 256 : N / 2;
        for (int j = threadIdx.x; j < nb2; j += blockDim.x)
            if (bat[2 * (base + j) + 1]) atomicOr(&s_b, 1);
        __syncthreads();
        if (threadIdx.x == 0) { g_ei64 = s_ei ? 0 : 1; g_b64 = s_b ? 0 : 1; }
    }
}

__device__ __forceinline__ int load_idx(const void* p, int i, int is64) {
    return is64 ? (int)((const long long*)p)[i] : ((const int*)p)[i];
}

// ---------------------------------------------------------------------------
// CSR-by-dst preprocessing
// ---------------------------------------------------------------------------
__global__ void k_hist(const void* __restrict__ ei, int E) {
    int e = blockIdx.x * blockDim.x + threadIdx.x;
    if (e >= E) return;
    atomicAdd(&g_deg[load_idx(ei, E + e, g_ei64)], 1);
}

// Single-pass exclusive scan, warp-parallel decoupled lookback.
// All <=64 blocks resident in wave 1; each publishes (blocksum+1) into one
// atomic word BEFORE polling, so no deadlock. Warp 0's lanes poll distinct
// predecessors concurrently, then shuffle-reduce.
__global__ void k_scan1(const int* __restrict__ in, int* __restrict__ off,
                        int* __restrict__ cur, int n, int E) {
    __shared__ int s[1024];
    __shared__ int s_pfx;
    int bid = blockIdx.x;
    int gid = bid * 1024 + threadIdx.x;
    int v = (gid < n) ? in[gid] : 0;
    s[threadIdx.x] = v;
    __syncthreads();
    #pragma unroll
    for (int d = 1; d < 1024; d <<= 1) {
        int t = (threadIdx.x >= d) ? s[threadIdx.x - d] : 0;
        __syncthreads();
        s[threadIdx.x] += t;
        __syncthreads();
    }
    if (threadIdx.x < 32) {
        if (threadIdx.x == 0)
            atomicExch(&g_flag[bid], s[1023] + 1);
        int pfx = 0;
        for (int i = threadIdx.x; i < bid; i += 32) {
            int f;
            while ((f = atomicAdd(&g_flag[i], 0)) == 0) {}
            pfx += f - 1;
        }
        #pragma unroll
        for (int o = 16; o > 0; o >>= 1)
            pfx += __shfl_down_sync(0xFFFFFFFFu, pfx, o);
        if (threadIdx.x == 0) s_pfx = pfx;
    }
    __syncthreads();
    if (gid < n) {
        int o = s_pfx + s[threadIdx.x] - v;
        off[gid] = o;
        cur[gid] = o;
    }
    if (bid == (int)gridDim.x - 1 && threadIdx.x == 1023) off[n] = E;
}

__global__ void k_scatter(const void* __restrict__ ei, int E) {
    int e = blockIdx.x * blockDim.x + threadIdx.x;
    if (e >= E) return;
    int is64 = g_ei64;
    int s = load_idx(ei, e, is64);
    int d = load_idx(ei, E + e, is64);
    int p = atomicAdd(&g_cur[d], 1);
    float w = rsqrtf((float)(g_deg[s] + 1));
    g_sw[p] = make_int2(s, __float_as_int(w));
}

// All three weights, transposed to [N x K] fp16, in one launch.
__global__ void k_cvtW(const float* __restrict__ W1, const float* __restrict__ W2,
                       const float* __restrict__ W3) {
    int t = blockIdx.x * blockDim.x + threadIdx.x;
    if (t < 131072) {                       // B1: N=256, K=512
        int n = t >> 9, k = t & 511;
        g_B1[t] = __float2half_rn(W1[(size_t)k * 256 + n]);
    } else if (t < 131072 + 32768) {        // B2: N=128, K=256
        int u = t - 131072;
        int n = u >> 8, k = u & 255;
        g_B2[u] = __float2half_rn(W2[(size_t)k * 128 + n]);
    } else if (t < 131072 + 32768 + 8192) { // B3: N=64, K=128
        int u = t - 163840;
        int n = u >> 7, k = u & 127;
        g_B3[u] = __float2half_rn(W3[(size_t)k * 64 + n]);
    }
}

// ---------------------------------------------------------------------------
// HMMA GEMM: C[M,N] = A[M,K] @ B[N,K]^T, fp32 accum, fp16 out.
// Grid: (n-tiles, m-tiles) -> bn = blockIdx.x (fastest) so CTAs sharing a bm
// run back-to-back and the second A read hits L2.
// CVT=true: A fp32 in gmem, register-staged LDG->cvt->STS double-buffered.
// ---------------------------------------------------------------------------
template<int BN, bool CVT>
__global__ void __launch_bounds__(256, 1) k_gemm_mma(
    const void* __restrict__ Av, const __half* __restrict__ B,
    __half* __restrict__ C, int M, int N, int K)
{
    constexpr int SS = 8192 + BN * 64;
    constexpr int NT = BN / 16;
    constexpr int WN = BN / 2;
    extern __shared__ char smem[];
    uint32_t sb = smem_u32(smem);
    int tid = threadIdx.x, lane = tid & 31, wid = tid >> 5;
    int bm = blockIdx.y * 128, bn = blockIdx.x * BN;
    int warp_m = wid & 3, warp_n = wid >> 2;
    const __half* A = (const __half*)Av;
    const float* Af = (const float*)Av;

    float acc[2][NT][4] = {};
    const int KC = K >> 5;
    float4 a4[4];

    auto ldgA = [&](int it) {
        int k0 = it << 5;
        #pragma unroll
        for (int u = 0; u < 4; u++) {
            int c = u * 256 + tid;
            int row = c >> 3, ch8 = c & 7;
            int grow = bm + row;
            if (grow < M)
                a4[u] = *(const float4*)(Af + (size_t)grow * K + k0 + ch8 * 4);
            else
                a4[u] = make_float4(0.f, 0.f, 0.f, 0.f);
        }
    };
    auto stsA = [&](int s) {
        uint32_t base = sb + s * SS;
        #pragma unroll
        for (int u = 0; u < 4; u++) {
            int c = u * 256 + tid;
            int row = c >> 3, ch8 = c & 7;
            uint32_t off = tile_off(row, ch8 >> 1) + (ch8 & 1) * 8;
            __half2 h0 = __floats2half2_rn(a4[u].x, a4[u].y);
            __half2 h1 = __floats2half2_rn(a4[u].z, a4[u].w);
            asm volatile("st.shared.v2.b32 [%0], {%1,%2};"
                         :: "r"(base + off), "r"(*(uint32_t*)&h0), "r"(*(uint32_t*)&h1));
        }
    };
    auto ldA_async = [&](int it, int s) {
        int k0 = it << 5;
        uint32_t base = sb + s * SS;
        #pragma unroll
        for (int u = 0; u < 2; u++) {
            int c = tid * 2 + u;
            int row = c >> 2, ch = c & 3;
            cpa16(base + tile_off(row, ch), A + (size_t)(bm + row) * K + k0 + ch * 8);
        }
    };
    auto ldB = [&](int it, int s) {
        int k0 = it << 5;
        uint32_t base = sb + s * SS;
        #pragma unroll
        for (int u = 0; u < BN / 64; u++) {
            int c = tid + u * 256;
            int row = c >> 2, ch = c & 3;
            cpa16(base + 8192 + tile_off(row, ch), B + (size_t)(bn + row) * K + k0 + ch * 8);
        }
    };

    if constexpr (CVT) {
        ldgA(0);
        ldB(0, 0);
        asm volatile("cp.async.commit_group;");
        stsA(0);
    } else {
        ldA_async(0, 0);
        ldB(0, 0);
        asm volatile("cp.async.commit_group;");
    }

    int a_row = warp_m * 32 + (lane & 15);
    int a_chi = lane >> 4;
    int blk = lane >> 3;
    int b_rl = ((blk >> 1) * 8) + (lane & 7);
    int b_chi = blk & 1;

    for (int it = 0; it < KC; it++) {
        int s = it & 1;
        if (it + 1 < KC) {
            if constexpr (CVT) {
                ldgA(it + 1);
                ldB(it + 1, s ^ 1);
            } else {
                ldA_async(it + 1, s ^ 1);
                ldB(it + 1, s ^ 1);
            }
            asm volatile("cp.async.commit_group;");
            asm volatile("cp.async.wait_group 1;");
        } else {
            asm volatile("cp.async.wait_group 0;");
        }
        __syncthreads();
        uint32_t base = sb + s * SS;
        #pragma unroll
        for (int kk = 0; kk < 2; kk++) {
            uint32_t af[2][4];
            int ach = kk * 2 + a_chi;
            #pragma unroll
            for (int mt = 0; mt < 2; mt++) {
                uint32_t off = tile_off(a_row + mt * 16, ach);
                LDM4(af[mt], base + off);
            }
            #pragma unroll
            for (int h = 0; h < NT / 4; h++) {
                uint32_t bf[4][2];
                #pragma unroll
                for (int nt2 = 0; nt2 < 2; nt2++) {
                    uint32_t r4[4];
                    int brow = warp_n * WN + h * 32 + nt2 * 16 + b_rl;
                    uint32_t off = tile_off(brow, kk * 2 + b_chi);
                    LDM4(r4, base + 8192 + off);
                    bf[nt2 * 2][0] = r4[0]; bf[nt2 * 2][1] = r4[1];
                    bf[nt2 * 2 + 1][0] = r4[2]; bf[nt2 * 2 + 1][1] = r4[3];
                }
                #pragma unroll
                for (int mt = 0; mt < 2; mt++)
                    #pragma unroll
                    for (int j = 0; j < 4; j++)
                        MMAF16(acc[mt][h * 4 + j], af[mt], bf[j]);
            }
        }
        __syncthreads();
        if constexpr (CVT) {
            if (it + 1 < KC) stsA(s ^ 1);
        }
    }

    #pragma unroll
    for (int mt = 0; mt < 2; mt++)
        #pragma unroll
        for (int nt = 0; nt < NT; nt++) {
            int row0 = bm + warp_m * 32 + mt * 16 + (lane >> 2);
            int col = bn + warp_n * WN + nt * 8 + (lane & 3) * 2;
            if (row0 < M)
                *(__half2*)(C + (size_t)row0 * N + col) =
                    __floats2half2_rn(acc[mt][nt][0], acc[mt][nt][1]);
            if (row0 + 8 < M)
                *(__half2*)(C + (size_t)(row0 + 8) * N + col) =
                    __floats2half2_rn(acc[mt][nt][2], acc[mt][nt][3]);
        }
}

// ---------------------------------------------------------------------------
// Aggregation over fp16 H: Out[v] = dinv[v]*(dinv[v]*H[v] + sum wt*H[src]) + b
// Each thread covers 8 features (one uint4); fp32 accumulate; packed (src,wt)
// edge records; 8x unrolled gather for MLP.
// ---------------------------------------------------------------------------
__global__ void k_agg(const __half* __restrict__ Hin, float* __restrict__ OutF,
                      __half* __restrict__ OutH,
                      const float* __restrict__ bias, int N, int Mpad, int relu) {
    int v = blockIdx.x * blockDim.y + threadIdx.y;
    if (v >= Mpad) return;
    int F8 = blockDim.x;
    int x = threadIdx.x;
    int F = F8 * 8;
    if (v >= N) {
        if (OutH)
            ((uint4*)(OutH + (size_t)v * F))[x] = make_uint4(0, 0, 0, 0);
        return;
    }
    const uint4* H4 = (const uint4*)Hin;
    float dv = rsqrtf((float)(g_deg[v] + 1));
    float acc[8];
    {
        uint4 hv = H4[(size_t)v * F8 + x];
        const __half2* p = (const __half2*)&hv;
        #pragma unroll
        for (int q = 0; q < 4; q++) {
            float2 f = __half22float2(p[q]);
            acc[q * 2] = dv * f.x;
            acc[q * 2 + 1] = dv * f.y;
        }
    }
    int e = g_off[v], end = g_off[v + 1];
    for (; e + 7 < end; e += 8) {
        int2 sw[8]; uint4 hv[8];
        #pragma unroll
        for (int j = 0; j < 8; j++)
            sw[j] = __ldg(&g_sw[e + j]);
        #pragma unroll
        for (int j = 0; j < 8; j++)
            hv[j] = H4[(size_t)sw[j].x * F8 + x];
        #pragma unroll
        for (int j = 0; j < 8; j++) {
            float w = __int_as_float(sw[j].y);
            const __half2* p = (const __half2*)&hv[j];
            #pragma unroll
            for (int q = 0; q < 4; q++) {
                float2 f = __half22float2(p[q]);
                acc[q * 2]     += w * f.x;
                acc[q * 2 + 1] += w * f.y;
            }
        }
    }
    for (; e + 3 < end; e += 4) {
        int2 sw[4]; uint4 hv[4];
        #pragma unroll
        for (int j = 0; j < 4; j++)
            sw[j] = __ldg(&g_sw[e + j]);
        #pragma unroll
        for (int j = 0; j < 4; j++)
            hv[j] = H4[(size_t)sw[j].x * F8 + x];
        #pragma unroll
        for (int j = 0; j < 4; j++) {
            float w = __int_as_float(sw[j].y);
            const __half2* p = (const __half2*)&hv[j];
            #pragma unroll
            for (int q = 0; q < 4; q++) {
                float2 f = __half22float2(p[q]);
                acc[q * 2]     += w * f.x;
                acc[q * 2 + 1] += w * f.y;
            }
        }
    }
    for (; e < end; e++) {
        int2 sw = __ldg(&g_sw[e]);
        float w = __int_as_float(sw.y);
        uint4 h0 = H4[(size_t)sw.x * F8 + x];
        const __half2* p0 = (const __half2*)&h0;
        #pragma unroll
        for (int q = 0; q < 4; q++) {
            float2 f0 = __half22float2(p0[q]);
            acc[q * 2]     += w * f0.x;
            acc[q * 2 + 1] += w * f0.y;
        }
    }
    float o[8];
    {
        float4 b0 = ((const float4*)bias)[x * 2];
        float4 b1 = ((const float4*)bias)[x * 2 + 1];
        o[0] = dv * acc[0] + b0.x; o[1] = dv * acc[1] + b0.y;
        o[2] = dv * acc[2] + b0.z; o[3] = dv * acc[3] + b0.w;
        o[4] = dv * acc[4] + b1.x; o[5] = dv * acc[5] + b1.y;
        o[6] = dv * acc[6] + b1.z; o[7] = dv * acc[7] + b1.w;
    }
    if (relu) {
        #pragma unroll
        for (int q = 0; q < 8; q++) o[q] = fmaxf(o[q], 0.f);
    }
    if (OutF) {
        float4* d = (float4*)(OutF + (size_t)v * F + x * 8);
        d[0] = make_float4(o[0], o[1], o[2], o[3]);
        d[1] = make_float4(o[4], o[5], o[6], o[7]);
    }
    if (OutH) {
        __half2 hh[4];
        #pragma unroll
        for (int q = 0; q < 4; q++)
            hh[q] = __floats2half2_rn(o[q * 2], o[q * 2 + 1]);
        ((uint4*)(OutH + (size_t)v * F))[x] = *(uint4*)hh;
    }
}

// ---------------------------------------------------------------------------
// Fused mean-pool + head: one block per graph (batch sorted).
// ---------------------------------------------------------------------------
__global__ void k_poolfinal(const float* __restrict__ Afin,
                            const void* __restrict__ bat,
                            const float* __restrict__ Wl,
                            const float* __restrict__ bl,
                            float* __restrict__ out, int N) {
    int g = blockIdx.x;
    int t = threadIdx.x;
    int is64 = g_b64;
    int lo = 0, hi = N;
    while (lo < hi) { int m = (lo + hi) >> 1; if (load_idx(bat, m, is64) < g) lo = m + 1; else hi = m; }
    int lo2 = lo, hi2 = N;
    while (lo2 < hi2) { int m = (lo2 + hi2) >> 1; if (load_idx(bat, m, is64) < g + 1) lo2 = m + 1; else hi2 = m; }
    int f = t & 63, seg = t >> 6;
    float acc = 0.f;
    for (int v = lo + seg; v < lo2; v += 4)
        acc += Afin[(size_t)v * 64 + f];
    __shared__ float sm[256];
    __shared__ float pooled[64];
    sm[t] = acc;
    __syncthreads();
    if (t < 64)
        pooled[t] = sm[t] + sm[t + 64] + sm[t + 128] + sm[t + 192];
    __syncthreads();
    if (t < 2) {
        float cnt = fmaxf((float)(lo2 - lo), 1.0f);
        float s = 0.f;
        #pragma unroll
        for (int ff = 0; ff < 64; ff++) s += pooled[ff] * Wl[ff * 2 + t];
        out[g * 2 + t] = s / cnt + bl[t];
    }
}

// ---------------------------------------------------------------------------
// Orchestration
// ---------------------------------------------------------------------------
extern "C" void kernel_launch(void* const* d_in, const int* in_sizes, int n_in,
                              void* d_out, int out_size) {
    const float* x   = (const float*)d_in[0];
    const void*  ei  = d_in[1];
    const void*  bat = d_in[2];
    const float* W1 = (const float*)d_in[3];
    const float* b1 = (const float*)d_in[4];
    const float* W2 = (const float*)d_in[5];
    const float* b2 = (const float*)d_in[6];
    const float* W3 = (const float*)d_in[7];
    const float* b3 = (const float*)d_in[8];
    const float* Wl = (const float*)d_in[9];
    const float* bl = (const float*)d_in[10];
    float* out = (float*)d_out;

    int N = in_sizes[0] / 512;
    int E = in_sizes[1] / 2;
    int G = out_size / 2;
    int mt = (N + 127) / 128;
    int Mpad = mt * 128;

    static int inited = 0;
    static cudaStream_t s2, s3;
    static cudaEvent_t ev1, ev_w, ev_csr;
    if (!inited) {
        cudaFuncSetAttribute((const void*)k_gemm_mma<128, true>,
                             cudaFuncAttributeMaxDynamicSharedMemorySize, 32768);
        cudaFuncSetAttribute((const void*)k_gemm_mma<128, false>,
                             cudaFuncAttributeMaxDynamicSharedMemorySize, 32768);
        cudaFuncSetAttribute((const void*)k_gemm_mma<64, false>,
                             cudaFuncAttributeMaxDynamicSharedMemorySize, 24576);
        cudaStreamCreateWithFlags(&s2, cudaStreamNonBlocking);
        cudaStreamCreateWithFlags(&s3, cudaStreamNonBlocking);
        cudaEventCreateWithFlags(&ev1, cudaEventDisableTiming);
        cudaEventCreateWithFlags(&ev_w, cudaEventDisableTiming);
        cudaEventCreateWithFlags(&ev_csr, cudaEventDisableTiming);
        inited = 1;
    }

    void *p_deg, *p_off, *p_cur, *p_H, *p_A, *p_X, *p_B1, *p_B2, *p_B3;
    cudaGetSymbolAddress(&p_deg, g_deg);
    cudaGetSymbolAddress(&p_off, g_off);
    cudaGetSymbolAddress(&p_cur, g_cur);
    cudaGetSymbolAddress(&p_H, g_H);
    cudaGetSymbolAddress(&p_A, g_A);
    cudaGetSymbolAddress(&p_X, g_X);
    cudaGetSymbolAddress(&p_B1, g_B1);
    cudaGetSymbolAddress(&p_B2, g_B2);
    cudaGetSymbolAddress(&p_B3, g_B3);

    // ---- fork -----------------------------------------------------------
    cudaEventRecord(ev1, 0);
    cudaStreamWaitEvent(s2, ev1, 0);
    cudaStreamWaitEvent(s3, ev1, 0);
    // s3: weight convert only (gates gemm1)
    k_cvtW<<<(172032 + 255) / 256, 256, 0, s3>>>(W1, W2, W3);
    cudaEventRecord(ev_w, s3);
    // s2: CSR build (gates agg1)
    k_detect<<<64, 256, 0, s2>>>((const unsigned*)ei, (const unsigned*)bat, E, N);
    k_hist<<<(E + 255) / 256, 256, 0, s2>>>(ei, E);
    int nb = (N + 1023) / 1024;
    k_scan1<<<nb, 1024, 0, s2>>>((const int*)p_deg, (int*)p_off, (int*)p_cur, N, E);
    k_scatter<<<(E + 255) / 256, 256, 0, s2>>>(ei, E);
    cudaEventRecord(ev_csr, s2);

    // ---- main: layer-1 GEMM with fused fp32->fp16 conversion ------------
    cudaStreamWaitEvent(0, ev_w, 0);
    k_gemm_mma<128, true><<<dim3(2, mt), 256, 32768>>>(
        x, (const __half*)p_B1, (__half*)p_H, N, 256, 512);

    // ---- join: aggregation needs CSR ------------------------------------
    cudaStreamWaitEvent(0, ev_csr, 0);
    {
        int gb = (Mpad + 7) / 8;
        k_agg<<<gb, dim3(32, 8)>>>((const __half*)p_H, nullptr,
                                   (__half*)p_X, b1, N, Mpad, 1);
    }
    // ---- layer 2 --------------------------------------------------------
    {
        k_gemm_mma<128, false><<<dim3(1, mt), 256, 32768>>>(
            p_X, (const __half*)p_B2, (__half*)p_H, N, 128, 256);
        int gb = (Mpad + 15) / 16;
        k_agg<<<gb, dim3(16, 16)>>>((const __half*)p_H, nullptr,
                                    (__half*)p_X, b2, N, Mpad, 1);
    }
    // ---- layer 3 --------------------------------------------------------
    {
        k_gemm_mma<64, false><<<dim3(1, mt), 256, 24576>>>(
            p_X, (const __half*)p_B3, (__half*)p_H, N, 64, 128);
        int gb = (N + 31) / 32;
        k_agg<<<gb, dim3(8, 32)>>>((const __half*)p_H, (float*)p_A,
                                   nullptr, b3, N, N, 0);
    }

    // ---- fused pool + head ----------------------------------------------
    k_poolfinal<<<G, 256>>>((const float*)p_A, bat, Wl, bl, out, N);
}